// round 5
// baseline (speedup 1.0000x reference)
#include <cuda_runtime.h>
#include <math.h>
#include <stdint.h>

// Problem constants
constexpr int cB  = 16;
constexpr int cH  = 8;
constexpr int cNL = 256;
constexpr int cNP = 2048;
constexpr int cD  = 64;          // HID
constexpr int cNT = cNL + cNP;   // 2304

// ---------------- scratch (device globals; no runtime allocation) ----------------
__device__ float g_L1 [cB * cH * cNL * cD];         // [bh][l][d]
__device__ float g_L2t[cB * cH * cD * cNL];         // [bh][d][l]
__device__ float g_P1 [cB * cH * cNP * cD];         // [bh][p][d]
__device__ float g_P2t[cB * cH * cD * cNP];         // [bh][d][p]
__device__ float g_att[(size_t)cB * cH * cNL * cNP];// e = exp(logit - rowmax), tf32
__device__ float g_sinv[cB * cH * cNL];             // 1 / row-sum of e
__device__ float g_l3h[cB * cNL * cH * cD];         // [B, Nl, 512]
__device__ float g_p3h[cB * cNP * cH * cD];         // [B, Np, 512]
__device__ float g_y1l[cB * cNL * cD];
__device__ float g_y1p[cB * cNP * cD];

// ---------------- tf32 helpers ----------------
__device__ __forceinline__ float tf32f(float x) {
    uint32_t u;
    asm("cvt.rna.tf32.f32 %0, %1;" : "=r"(u) : "f"(x));
    return __uint_as_float(u);
}

__device__ __forceinline__ void mma_tf32(float d[4], const uint32_t a[4], const uint32_t b[2]) {
    asm volatile(
        "mma.sync.aligned.m16n8k8.row.col.f32.tf32.tf32.f32 "
        "{%0,%1,%2,%3}, {%4,%5,%6,%7}, {%8,%9}, {%0,%1,%2,%3};\n"
        : "+f"(d[0]), "+f"(d[1]), "+f"(d[2]), "+f"(d[3])
        : "r"(a[0]), "r"(a[1]), "r"(a[2]), "r"(a[3]), "r"(b[0]), "r"(b[1]));
}

__device__ __forceinline__ void mma_tf32_f4(float d[4], const float4 av, const float2 bv) {
    uint32_t a[4] = { __float_as_uint(av.x), __float_as_uint(av.y),
                      __float_as_uint(av.z), __float_as_uint(av.w) };
    uint32_t b[2] = { __float_as_uint(bv.x), __float_as_uint(bv.y) };
    mma_tf32(d, a, b);
}

// Fragment-major permuted smem indices (m16n8k8):
//  A tile: logical (r,k) of an Mx(KT*8) tile -> perm index; lane fragment = float4
__device__ __forceinline__ int a_idx(int r, int k, int KT) {
    int mt = r >> 4, grp = r & 7, e0 = (r >> 3) & 1;
    int kt = k >> 3, qid = k & 3, e1 = (k >> 2) & 1;
    return ((mt * KT + kt) * 32 + grp * 4 + qid) * 4 + (e0 + (e1 << 1));
}
//  B tile: logical (n,k) -> perm index; lane fragment = float2
__device__ __forceinline__ int b_idx(int n, int k, int KT) {
    int nt = n >> 3, grp = n & 7;
    int kt = k >> 3, qid = k & 3, e = (k >> 2) & 1;
    return ((nt * KT + kt) * 32 + grp * 4 + qid) * 2 + e;
}

#define CS(r_, c_) SM[(r_) * 68 + (c_)]   // stage buffer [64][68], aliases SM head

// =====================================================================
// Projection (tf32 MMA): out = relu(x @ w[:, h*64:h*64+64] + b), per head.
// which 0 (L1) / 2 (P1): [bh][n][d].  which 1 (L2t) / 3 (P2t): [bh][d][n].
// =====================================================================
__global__ __launch_bounds__(256) void proj_mma(const float* __restrict__ x,
                                                const float* __restrict__ w,
                                                const float* __restrict__ bias,
                                                int N, int which) {
    float* out = (which == 0) ? g_L1 : (which == 1) ? g_L2t : (which == 2) ? g_P1 : g_P2t;
    const bool tr = (which == 1) || (which == 3);
    __shared__ float SM[8192];           // Ap[0..4095] | Bp[4096..8191]; CS aliases head
    float* Ap = SM;
    float* Bp = SM + 4096;
    const int row0 = blockIdx.x * 64;
    const int h = blockIdx.y;
    const int tid = threadIdx.x;

    for (int i = tid; i < 4096; i += 256) {
        int r = i >> 6, k = i & 63;
        Ap[a_idx(r, k, 8)] = tf32f(x[(size_t)(row0 + r) * 64 + k]);
    }
    for (int i = tid; i < 4096; i += 256) {
        int k = i >> 6, n = i & 63;
        Bp[b_idx(n, k, 8)] = tf32f(w[(size_t)k * 512 + h * 64 + n]);
    }
    __syncthreads();

    const int wid = tid >> 5, lane = tid & 31, grp = lane >> 2, qid = lane & 3;
    const int mtw = wid & 3, ntw = (wid >> 2) * 4;
    const int m0 = mtw * 16, n0 = (wid >> 2) * 32;
    float acc[4][4] = {};
#pragma unroll
    for (int kk = 0; kk < 8; kk++) {
        const float4 av = *(const float4*)&Ap[((mtw * 8 + kk) * 32 + lane) * 4];
#pragma unroll
        for (int t = 0; t < 4; t++) {
            const float2 bv = *(const float2*)&Bp[(((ntw + t) * 8 + kk) * 32 + lane) * 2];
            mma_tf32_f4(acc[t], av, bv);
        }
    }
    __syncthreads();

    const int r0l = m0 + grp, r1l = r0l + 8;
    if (!tr) {
#pragma unroll
        for (int t = 0; t < 4; t++) {
            int c = n0 + t * 8 + 2 * qid;
            float bv0 = bias[h * 64 + c], bv1 = bias[h * 64 + c + 1];
            CS(r0l, c)     = tf32f(fmaxf(acc[t][0] + bv0, 0.f));
            CS(r0l, c + 1) = tf32f(fmaxf(acc[t][1] + bv1, 0.f));
            CS(r1l, c)     = tf32f(fmaxf(acc[t][2] + bv0, 0.f));
            CS(r1l, c + 1) = tf32f(fmaxf(acc[t][3] + bv1, 0.f));
        }
        __syncthreads();
        const int b = row0 / N, nbase = row0 % N;   // 64 | N so one b per block
        for (int i = tid; i < 1024; i += 256) {
            int r = i >> 4, c4 = (i & 15) * 4;
            *(float4*)&out[(((size_t)b * cH + h) * N + nbase + r) * 64 + c4] =
                *(float4*)&CS(r, c4);
        }
    } else {
#pragma unroll
        for (int t = 0; t < 4; t++) {
            int c = n0 + t * 8 + 2 * qid;
            float bv0 = bias[h * 64 + c], bv1 = bias[h * 64 + c + 1];
            CS(c, r0l)     = tf32f(fmaxf(acc[t][0] + bv0, 0.f));
            CS(c + 1, r0l) = tf32f(fmaxf(acc[t][1] + bv1, 0.f));
            CS(c, r1l)     = tf32f(fmaxf(acc[t][2] + bv0, 0.f));
            CS(c + 1, r1l) = tf32f(fmaxf(acc[t][3] + bv1, 0.f));
        }
        __syncthreads();
        const int b = row0 / N, nbase = row0 % N;
        for (int i = tid; i < 1024; i += 256) {
            int d = i >> 4, r4 = (i & 15) * 4;
            *(float4*)&out[(((size_t)b * cH + h) * 64 + d) * N + nbase + r4] =
                *(float4*)&CS(d, r4);
        }
    }
}

// =====================================================================
// Energy (tf32 MMA) + band mask + stable softmax numerator, single launch:
//   pass 1: MMA -> logits -> row max only. pass 2: recompute -> e -> staged
//   coalesced writes to g_att; deterministic row sums -> g_sinv.
// =====================================================================
__global__ __launch_bounds__(256) void energy_mma(const float* __restrict__ dist) {
    __shared__ float SM[8192];           // Ap | Bp; CS aliases head (Ap dead after hoist)
    __shared__ float red2[2][64];
    __shared__ float rowmax_s[64];
    float* Ap = SM;
    float* Bp = SM + 4096;
    const int bh = blockIdx.y, b = bh >> 3, h = bh & 7;
    const int l0 = blockIdx.x * 64;
    const int tid = threadIdx.x;
    const int wid = tid >> 5, lane = tid & 31, grp = lane >> 2, qid = lane & 3;
    const int mtw = wid & 3, ntw = (wid >> 2) * 4;
    const int m0 = mtw * 16, n0 = (wid >> 2) * 32;

    const float* Apg = g_L1 + ((size_t)bh * cNL + l0) * 64;
    for (int i = tid; i < 4096; i += 256) {
        int r = i >> 6, k = i & 63;
        Ap[a_idx(r, k, 8)] = Apg[(size_t)r * 64 + k];
    }
    __syncthreads();

    // hoist A fragments to registers (fixed across the whole p loop)
    float4 afr[8];
#pragma unroll
    for (int kk = 0; kk < 8; kk++)
        afr[kk] = *(const float4*)&Ap[((mtw * 8 + kk) * 32 + lane) * 4];
    __syncthreads();   // Ap region may now be reused as CS

    const float* Bbase = g_P1 + (size_t)bh * cNP * 64;
    float* ebase = g_att + ((size_t)bh * cNL + l0) * cNP;
    const int lm0 = m0 + grp, lm1 = lm0 + 8;
    const size_t drow0 = ((size_t)(b * cNL) + l0 + lm0) * cNP;
    const size_t drow1 = ((size_t)(b * cNL) + l0 + lm1) * cNP;
    const float hf = (float)h;

    // ---- pass 1: row max only ----
    float mx0 = 0.f, mx1 = 0.f;    // masked entries carry logit 0
    for (int pt = 0; pt < 32; pt++) {
        const int p0 = pt * 64;
        __syncthreads();
        for (int i = tid; i < 4096; i += 256) {
            int p = i >> 6, k = i & 63;
            Bp[b_idx(p, k, 8)] = Bbase[(size_t)(p0 + p) * 64 + k];
        }
        __syncthreads();

        float acc[4][4] = {};
#pragma unroll
        for (int kk = 0; kk < 8; kk++) {
#pragma unroll
            for (int t = 0; t < 4; t++) {
                const float2 bv = *(const float2*)&Bp[(((ntw + t) * 8 + kk) * 32 + lane) * 2];
                mma_tf32_f4(acc[t], afr[kk], bv);
            }
        }

#pragma unroll
        for (int t = 0; t < 4; t++) {
            const int c = p0 + n0 + t * 8 + 2 * qid;
            const float2 dv0 = *(const float2*)&dist[drow0 + c];
            const float2 dv1 = *(const float2*)&dist[drow1 + c];
            const float dd[4] = {dv0.x, dv0.y, dv1.x, dv1.y};
#pragma unroll
            for (int j = 0; j < 4; j++) {
                const float d = dd[j];
                const bool m = (h < 7) ? (d > hf && d <= hf + 3.0f) : (d > 7.0f);
                const float inter = m ? __fdividef(1.0f, d) : 0.0f;
                const float lg = acc[t][j] * 0.125f * inter;
                if (j < 2) mx0 = fmaxf(mx0, lg); else mx1 = fmaxf(mx1, lg);
            }
        }
    }

    mx0 = fmaxf(mx0, __shfl_xor_sync(0xffffffffu, mx0, 1));
    mx0 = fmaxf(mx0, __shfl_xor_sync(0xffffffffu, mx0, 2));
    mx1 = fmaxf(mx1, __shfl_xor_sync(0xffffffffu, mx1, 1));
    mx1 = fmaxf(mx1, __shfl_xor_sync(0xffffffffu, mx1, 2));
    if (qid == 0) {
        red2[wid >> 2][lm0] = mx0;
        red2[wid >> 2][lm1] = mx1;
    }
    __syncthreads();
    if (tid < 64) rowmax_s[tid] = fmaxf(red2[0][tid], red2[1][tid]);
    __syncthreads();
    const float rm0 = rowmax_s[lm0], rm1 = rowmax_s[lm1];

    // ---- pass 2: recompute, e = exp(lg - rm), staged coalesced writes, sums ----
    float rs0 = 0.f, rs1 = 0.f;
    for (int pt = 0; pt < 32; pt++) {
        const int p0 = pt * 64;
        __syncthreads();
        for (int i = tid; i < 4096; i += 256) {
            int p = i >> 6, k = i & 63;
            Bp[b_idx(p, k, 8)] = Bbase[(size_t)(p0 + p) * 64 + k];
        }
        __syncthreads();

        float acc[4][4] = {};
#pragma unroll
        for (int kk = 0; kk < 8; kk++) {
#pragma unroll
            for (int t = 0; t < 4; t++) {
                const float2 bv = *(const float2*)&Bp[(((ntw + t) * 8 + kk) * 32 + lane) * 2];
                mma_tf32_f4(acc[t], afr[kk], bv);
            }
        }

#pragma unroll
        for (int t = 0; t < 4; t++) {
            const int c = p0 + n0 + t * 8 + 2 * qid;
            const float2 dv0 = *(const float2*)&dist[drow0 + c];
            const float2 dv1 = *(const float2*)&dist[drow1 + c];
            const float dd[4] = {dv0.x, dv0.y, dv1.x, dv1.y};
            float ev[4];
#pragma unroll
            for (int j = 0; j < 4; j++) {
                const float d = dd[j];
                const bool m = (h < 7) ? (d > hf && d <= hf + 3.0f) : (d > 7.0f);
                const float inter = m ? __fdividef(1.0f, d) : 0.0f;
                const float lg = acc[t][j] * 0.125f * inter;
                ev[j] = __expf(lg - (j < 2 ? rm0 : rm1));
            }
            rs0 += ev[0] + ev[1];
            rs1 += ev[2] + ev[3];
            const int cl = n0 + t * 8 + 2 * qid;
            CS(lm0, cl)     = tf32f(ev[0]);
            CS(lm0, cl + 1) = tf32f(ev[1]);
            CS(lm1, cl)     = tf32f(ev[2]);
            CS(lm1, cl + 1) = tf32f(ev[3]);
        }
        __syncthreads();
        for (int i = tid; i < 1024; i += 256) {
            int l = i >> 4, c4 = (i & 15) * 4;
            *(float4*)&ebase[(size_t)l * cNP + p0 + c4] = *(float4*)&CS(l, c4);
        }
    }

    rs0 += __shfl_xor_sync(0xffffffffu, rs0, 1);
    rs0 += __shfl_xor_sync(0xffffffffu, rs0, 2);
    rs1 += __shfl_xor_sync(0xffffffffu, rs1, 1);
    rs1 += __shfl_xor_sync(0xffffffffu, rs1, 2);
    if (qid == 0) {
        red2[wid >> 2][lm0] = rs0;
        red2[wid >> 2][lm1] = rs1;
    }
    __syncthreads();
    if (tid < 64) {
        g_sinv[bh * cNL + l0 + tid] = 1.0f / (red2[0][tid] + red2[1][tid]);
    }
}

// =====================================================================
// av (tf32 MMA): l3h[b,l,h*64+d] = (sum_p e[l,p] * P2t[d,p]) * sinv[l]
// =====================================================================
__global__ __launch_bounds__(256) void av_mma() {
    __shared__ float SM[8192];
    float* Ap = SM;
    float* Bp = SM + 4096;
    const int bh = blockIdx.y, b = bh >> 3, h = bh & 7;
    const int l0 = blockIdx.x * 64;
    const int tid = threadIdx.x, wid = tid >> 5, lane = tid & 31, grp = lane >> 2, qid = lane & 3;
    const int mtw = wid & 3, ntw = (wid >> 2) * 4;
    const int m0 = mtw * 16, n0 = (wid >> 2) * 32;
    const float* Ab = g_att + ((size_t)bh * cNL + l0) * cNP;
    const float* Bb = g_P2t + (size_t)bh * 64 * cNP;
    float acc[4][4] = {};

    for (int pt = 0; pt < 32; pt++) {
        const int p0 = pt * 64;
        __syncthreads();
        for (int i = tid; i < 4096; i += 256) {
            int r = i >> 6, k = i & 63;
            Ap[a_idx(r, k, 8)] = Ab[(size_t)r * cNP + p0 + k];
            Bp[b_idx(r, k, 8)] = Bb[(size_t)r * cNP + p0 + k];
        }
        __syncthreads();
#pragma unroll
        for (int kk = 0; kk < 8; kk++) {
            const float4 av = *(const float4*)&Ap[((mtw * 8 + kk) * 32 + lane) * 4];
#pragma unroll
            for (int t = 0; t < 4; t++) {
                const float2 bv = *(const float2*)&Bp[(((ntw + t) * 8 + kk) * 32 + lane) * 2];
                mma_tf32_f4(acc[t], av, bv);
            }
        }
    }

    const int lm0 = m0 + grp, lm1 = lm0 + 8;
    const float inv0 = g_sinv[bh * cNL + l0 + lm0];
    const float inv1 = g_sinv[bh * cNL + l0 + lm1];
    __syncthreads();
#pragma unroll
    for (int t = 0; t < 4; t++) {
        const int c = n0 + t * 8 + 2 * qid;
        CS(lm0, c)     = acc[t][0] * inv0;
        CS(lm0, c + 1) = acc[t][1] * inv0;
        CS(lm1, c)     = acc[t][2] * inv1;
        CS(lm1, c + 1) = acc[t][3] * inv1;
    }
    __syncthreads();
    for (int i = tid; i < 1024; i += 256) {
        int l = i >> 4, c4 = (i & 15) * 4;
        *(float4*)&g_l3h[((size_t)(b * cNL) + l0 + l) * 512 + h * 64 + c4] =
            *(float4*)&CS(l, c4);
    }
}

// =====================================================================
// atv (tf32 MMA): p3h[b,p,h*64+d] = sum_l e[l,p] * (L2t[d,l] * sinv[l])
// Block = 128 p x 64 d, K = 256 in tiles of 32.
// =====================================================================
__global__ __launch_bounds__(256) void atv_mma() {
    __shared__ float SM[6144];           // Ap[4096] | Bp[2048]; CS aliases head
    float* Ap = SM;
    float* Bp = SM + 4096;
    const int bh = blockIdx.y, b = bh >> 3, h = bh & 7;
    const int p0 = blockIdx.x * 128;
    const int tid = threadIdx.x, wid = tid >> 5, lane = tid & 31, grp = lane >> 2, qid = lane & 3;
    const int m0 = wid * 16;
    const float* eb = g_att + (size_t)bh * cNL * cNP;
    const float* L2b = g_L2t + (size_t)bh * 64 * cNL;
    const float* sv = g_sinv + (size_t)bh * cNL;
    float acc[8][4] = {};

    for (int lt = 0; lt < 8; lt++) {
        const int lb = lt * 32;
        __syncthreads();
        for (int i = tid; i < 4096; i += 256) {
            int r = i >> 7, c = i & 127;     // r = l local (k), c = p local (m)
            Ap[a_idx(c, r, 4)] = eb[(size_t)(lb + r) * cNP + p0 + c];
        }
        for (int i = tid; i < 2048; i += 256) {
            int d = i >> 5, k = i & 31;
            Bp[b_idx(d, k, 4)] = tf32f(L2b[(size_t)d * cNL + lb + k] * sv[lb + k]);
        }
        __syncthreads();
#pragma unroll
        for (int kk = 0; kk < 4; kk++) {
            const float4 av = *(const float4*)&Ap[((wid * 4 + kk) * 32 + lane) * 4];
#pragma unroll
            for (int t = 0; t < 8; t++) {
                const float2 bv = *(const float2*)&Bp[((t * 4 + kk) * 32 + lane) * 2];
                mma_tf32_f4(acc[t], av, bv);
            }
        }
    }

    // staged epilogue, two halves of 64 p-rows each
#pragma unroll
    for (int half = 0; half < 2; half++) {
        __syncthreads();
        if ((wid >> 2) == half) {
            const int pl0 = (m0 & 63) + grp, pl1 = pl0 + 8;
#pragma unroll
            for (int t = 0; t < 8; t++) {
                const int c = t * 8 + 2 * qid;
                CS(pl0, c)     = acc[t][0];
                CS(pl0, c + 1) = acc[t][1];
                CS(pl1, c)     = acc[t][2];
                CS(pl1, c + 1) = acc[t][3];
            }
        }
        __syncthreads();
        const int pg = p0 + half * 64;
        for (int i = tid; i < 1024; i += 256) {
            int pl = i >> 4, c4 = (i & 15) * 4;
            *(float4*)&g_p3h[((size_t)(b * cNP) + pg + pl) * 512 + h * 64 + c4] =
                *(float4*)&CS(pl, c4);
        }
    }
}

// =====================================================================
// fc1 (tf32 MMA): Y[row,d] = X[row,:512] @ W[512,64] + bias
// =====================================================================
__global__ __launch_bounds__(256) void fc1_mma(const float* __restrict__ w,
                                               const float* __restrict__ bias, int which) {
    const float* X = which ? g_p3h : g_l3h;
    float* Y = which ? g_y1p : g_y1l;
    __shared__ float SM[8192];
    float* Ap = SM;
    float* Bp = SM + 4096;
    const int row0 = blockIdx.x * 64;
    const int tid = threadIdx.x, wid = tid >> 5, lane = tid & 31, grp = lane >> 2, qid = lane & 3;
    const int mtw = wid & 3, ntw = (wid >> 2) * 4;
    const int m0 = mtw * 16, n0 = (wid >> 2) * 32;
    float acc[4][4] = {};

    for (int kt = 0; kt < 8; kt++) {
        const int kb = kt * 64;
        __syncthreads();
        for (int i = tid; i < 4096; i += 256) {
            int r = i >> 6, k = i & 63;
            Ap[a_idx(r, k, 8)] = tf32f(X[(size_t)(row0 + r) * 512 + kb + k]);
        }
        for (int i = tid; i < 4096; i += 256) {
            int k = i >> 6, n = i & 63;
            Bp[b_idx(n, k, 8)] = tf32f(w[(size_t)(kb + k) * 64 + n]);
        }
        __syncthreads();
#pragma unroll
        for (int kk = 0; kk < 8; kk++) {
            const float4 av = *(const float4*)&Ap[((mtw * 8 + kk) * 32 + lane) * 4];
#pragma unroll
            for (int t = 0; t < 4; t++) {
                const float2 bv = *(const float2*)&Bp[(((ntw + t) * 8 + kk) * 32 + lane) * 2];
                mma_tf32_f4(acc[t], av, bv);
            }
        }
    }

    __syncthreads();
    const int r0l = m0 + grp, r1l = r0l + 8;
#pragma unroll
    for (int t = 0; t < 4; t++) {
        const int c = n0 + t * 8 + 2 * qid;
        const float bv0 = bias[c], bv1 = bias[c + 1];
        CS(r0l, c)     = acc[t][0] + bv0;
        CS(r0l, c + 1) = acc[t][1] + bv1;
        CS(r1l, c)     = acc[t][2] + bv0;
        CS(r1l, c + 1) = acc[t][3] + bv1;
    }
    __syncthreads();
    for (int i = tid; i < 1024; i += 256) {
        int r = i >> 4, c4 = (i & 15) * 4;
        *(float4*)&Y[(size_t)(row0 + r) * 64 + c4] = *(float4*)&CS(r, c4);
    }
}

// =====================================================================
// fc2 (fp32, fused concat): out = relu( [Y1, orig] @ W[128,64] + bias )
// =====================================================================
__global__ __launch_bounds__(256) void fc2_kernel(const float* __restrict__ orig,
                                                  const float* __restrict__ w,
                                                  const float* __restrict__ bias,
                                                  float* __restrict__ out,
                                                  int N, int which, int row_off) {
    const float* Y1 = which ? g_y1p : g_y1l;
    __shared__ float As[32][68];
    __shared__ float Bs[32][68];
    const int row0 = blockIdx.x * 64;
    const int tid = threadIdx.x, ty = tid >> 4, tx = tid & 15;
    float acc[4][4] = {};

    for (int k0 = 0; k0 < 128; k0 += 32) {
        const float* src = (k0 < 64) ? Y1 : orig;
        const int kb = k0 & 63;
        for (int i = tid; i < 64 * 32; i += 256) {
            int r = i >> 5, k = i & 31;
            As[k][r] = src[(size_t)(row0 + r) * 64 + kb + k];
        }
        for (int i = tid; i < 32 * 64; i += 256) {
            int k = i >> 6, c = i & 63;
            Bs[k][c] = w[(size_t)(k0 + k) * 64 + c];
        }
        __syncthreads();
#pragma unroll
        for (int k = 0; k < 32; k++) {
            float4 a4 = *(const float4*)&As[k][ty * 4];
            float4 b4 = *(const float4*)&Bs[k][tx * 4];
            float a[4] = {a4.x, a4.y, a4.z, a4.w};
            float bb[4] = {b4.x, b4.y, b4.z, b4.w};
#pragma unroll
            for (int i = 0; i < 4; i++)
#pragma unroll
                for (int j = 0; j < 4; j++) acc[i][j] = fmaf(a[i], bb[j], acc[i][j]);
        }
        __syncthreads();
    }

#pragma unroll
    for (int i = 0; i < 4; i++) {
        int row = row0 + ty * 4 + i;
        int b = row / N, n = row % N;
        float4 o;
        float* op = (float*)&o;
#pragma unroll
        for (int j = 0; j < 4; j++)
            op[j] = fmaxf(acc[i][j] + bias[tx * 4 + j], 0.0f);
        *(float4*)&out[((size_t)b * cNT + row_off + n) * 64 + tx * 4] = o;
    }
}

// =====================================================================
extern "C" void kernel_launch(void* const* d_in, const int* in_sizes, int n_in,
                              void* d_out, int out_size) {
    (void)in_sizes; (void)n_in; (void)out_size;
    const float* ligand = (const float*)d_in[0];
    const float* prot   = (const float*)d_in[1];
    const float* dist   = (const float*)d_in[2];
    const float* w_l1 = (const float*)d_in[3];
    const float* b_l1 = (const float*)d_in[4];
    const float* w_l2 = (const float*)d_in[5];
    const float* b_l2 = (const float*)d_in[6];
    const float* w_p1 = (const float*)d_in[7];
    const float* b_p1 = (const float*)d_in[8];
    const float* w_p2 = (const float*)d_in[9];
    const float* b_p2 = (const float*)d_in[10];
    const float* fc11_w = (const float*)d_in[11];
    const float* fc11_b = (const float*)d_in[12];
    const float* fc12_w = (const float*)d_in[13];
    const float* fc12_b = (const float*)d_in[14];
    const float* fc21_w = (const float*)d_in[15];
    const float* fc21_b = (const float*)d_in[16];
    const float* fc22_w = (const float*)d_in[17];
    const float* fc22_b = (const float*)d_in[18];
    float* out = (float*)d_out;

    // Projections (tf32). L1/P1 natural layout; L2/P2 transposed [d][n].
    proj_mma<<<dim3(cB * cNL / 64, cH), 256>>>(ligand, w_l1, b_l1, cNL, 0);
    proj_mma<<<dim3(cB * cNL / 64, cH), 256>>>(ligand, w_l2, b_l2, cNL, 1);
    proj_mma<<<dim3(cB * cNP / 64, cH), 256>>>(prot, w_p1, b_p1, cNP, 2);
    proj_mma<<<dim3(cB * cNP / 64, cH), 256>>>(prot, w_p2, b_p2, cNP, 3);

    // Fused energy + mask + stable softmax numerator (max pass + recompute pass)
    energy_mma<<<dim3(cNL / 64, cB * cH), 256>>>(dist);

    // Attention GEMMs with normalization folded in
    av_mma<<<dim3(cNL / 64, cB * cH), 256>>>();
    atv_mma<<<dim3(cNP / 128, cB * cH), 256>>>();

    // FC heads
    fc1_mma<<<cB * cNL / 64, 256>>>(fc11_w, fc11_b, 0);
    fc1_mma<<<cB * cNP / 64, 256>>>(fc21_w, fc21_b, 1);
    fc2_kernel<<<cB * cNL / 64, 256>>>(ligand, fc12_w, fc12_b, out, cNL, 0, 0);
    fc2_kernel<<<cB * cNP / 64, 256>>>(prot, fc22_w, fc22_b, out, cNP, 1, cNL);
}

// round 6
// speedup vs baseline: 1.0543x; 1.0543x over previous
#include <cuda_runtime.h>
#include <math.h>
#include <stdint.h>

// Problem constants
constexpr int cB  = 16;
constexpr int cH  = 8;
constexpr int cNL = 256;
constexpr int cNP = 2048;
constexpr int cD  = 64;          // HID
constexpr int cNT = cNL + cNP;   // 2304

// ---------------- scratch (device globals; no runtime allocation) ----------------
__device__ float g_L1 [cB * cH * cNL * cD];         // [bh][l][d]   (tf32, relu)
__device__ float g_L2t[cB * cH * cD * cNL];         // [bh][d][l]
__device__ float g_P1 [cB * cH * cNP * cD];         // [bh][p][d]
__device__ float g_P2t[cB * cH * cD * cNP];         // [bh][d][p]
__device__ float g_att[(size_t)cB * cH * cNL * cNP];// e = exp(logit - rowmax), tf32
__device__ float g_sinv[cB * cH * cNL];             // 1 / row-sum of e
__device__ float g_l3h[cB * cNL * cH * cD];         // [B, Nl, 512] (tf32)
__device__ float g_p3h[cB * cNP * cH * cD];         // [B, Np, 512] (tf32)
// transposed + tf32-rounded weights
__device__ float g_wT [4][512 * 64];                // proj: [(h*64+n)][k]
__device__ float g_f1T[2][64 * 512];                // fc11/fc21: [n][k]
__device__ float g_f2T[2][64 * 128];                // fc12/fc22: [n][k]

// ---------------- tf32 helpers ----------------
__device__ __forceinline__ float tf32f(float x) {
    uint32_t u;
    asm("cvt.rna.tf32.f32 %0, %1;" : "=r"(u) : "f"(x));
    return __uint_as_float(u);
}

__device__ __forceinline__ void mma_tf32(float d[4], const uint32_t a[4], const uint32_t b[2]) {
    asm volatile(
        "mma.sync.aligned.m16n8k8.row.col.f32.tf32.tf32.f32 "
        "{%0,%1,%2,%3}, {%4,%5,%6,%7}, {%8,%9}, {%0,%1,%2,%3};\n"
        : "+f"(d[0]), "+f"(d[1]), "+f"(d[2]), "+f"(d[3])
        : "r"(a[0]), "r"(a[1]), "r"(a[2]), "r"(a[3]), "r"(b[0]), "r"(b[1]));
}

#define AS(r_, c_) As[(r_) * 68 + (c_)]
#define BS(r_, c_) Bs[(r_) * 68 + (c_)]
#define CS(r_, c_) As[(r_) * 68 + (c_)]   // stage aliases As region

__device__ __forceinline__ void load_afr(const float* As_, int m0, int grp, int qid,
                                         int kk, uint32_t a[4]) {
    const int k0 = kk * 8;
    a[0] = __float_as_uint(As_[(m0 + grp) * 68 + k0 + qid]);
    a[1] = __float_as_uint(As_[(m0 + grp + 8) * 68 + k0 + qid]);
    a[2] = __float_as_uint(As_[(m0 + grp) * 68 + k0 + qid + 4]);
    a[3] = __float_as_uint(As_[(m0 + grp + 8) * 68 + k0 + qid + 4]);
}

__device__ __forceinline__ void load_bfr(const float* Bs_, int n, int kk, int qid,
                                         uint32_t b[2]) {
    const int k0 = kk * 8;
    b[0] = __float_as_uint(Bs_[n * 68 + k0 + qid]);
    b[1] = __float_as_uint(Bs_[n * 68 + k0 + qid + 4]);
}

// =====================================================================
// prep: transpose + tf32-round all weights once.
// =====================================================================
__global__ __launch_bounds__(256) void prep_weights(
    const float* __restrict__ wl1, const float* __restrict__ wl2,
    const float* __restrict__ wp1, const float* __restrict__ wp2,
    const float* __restrict__ f11, const float* __restrict__ f21,
    const float* __restrict__ f12, const float* __restrict__ f22) {
    int i = blockIdx.x * 256 + threadIdx.x;
    if (i < 4 * 32768) {
        int w = i >> 15, r = i & 32767;          // r = hn*64 + k
        int hn = r >> 6, k = r & 63;
        const float* src = (w == 0) ? wl1 : (w == 1) ? wl2 : (w == 2) ? wp1 : wp2;
        g_wT[w][r] = tf32f(src[(size_t)k * 512 + hn]);
    } else if (i < 6 * 32768) {
        int j = i - 4 * 32768;
        int w = j >> 15, r = j & 32767;          // r = n*512 + k
        int n = r >> 9, k = r & 511;
        const float* src = w ? f21 : f11;
        g_f1T[w][r] = tf32f(src[(size_t)k * 64 + n]);
    } else if (i < 6 * 32768 + 2 * 8192) {
        int j = i - 6 * 32768;
        int w = j >> 13, r = j & 8191;           // r = n*128 + k
        int n = r >> 7, k = r & 127;
        const float* src = w ? f22 : f12;
        g_f2T[w][r] = tf32f(src[(size_t)k * 64 + n]);
    }
}

// =====================================================================
// proj2: both projections for one input. Block = 64 rows; x tile loaded once,
// A-fragments hoisted; loop over 16 (weight, head) B-tiles.
// wsel 0 -> natural [bh][n][d] (g_L1/g_P1); wsel 1 -> transposed [bh][d][n].
// =====================================================================
__global__ __launch_bounds__(256) void proj2(const float* __restrict__ x,
                                             const float* __restrict__ bA,
                                             const float* __restrict__ bB,
                                             int N, int which) {
    __shared__ float As[64 * 68];
    __shared__ float Bs[64 * 68];
    const int row0 = blockIdx.x * 64;
    const int tid = threadIdx.x;

    for (int i = tid; i < 1024; i += 256) {
        int r = i >> 4, c4 = (i & 15) * 4;
        float4 v = *(const float4*)&x[(size_t)(row0 + r) * 64 + c4];
        v.x = tf32f(v.x); v.y = tf32f(v.y); v.z = tf32f(v.z); v.w = tf32f(v.w);
        *(float4*)&AS(r, c4) = v;
    }
    __syncthreads();

    const int wid = tid >> 5, lane = tid & 31, grp = lane >> 2, qid = lane & 3;
    const int mtw = wid & 3, nw = wid >> 2;
    const int m0 = mtw * 16, n0 = nw * 32;
    uint32_t afr[8][4];
#pragma unroll
    for (int kk = 0; kk < 8; kk++) load_afr(As, m0, grp, qid, kk, afr[kk]);

    const int b = row0 / N, nbase = row0 % N;
    const int r0l = m0 + grp, r1l = r0l + 8;

    for (int it = 0; it < 16; it++) {
        const int wsel = it >> 3, h = it & 7;
        const float* wT = g_wT[which * 2 + wsel];
        const float* bias = wsel ? bB : bA;
        float* outp = (which == 0) ? (wsel ? g_L2t : g_L1) : (wsel ? g_P2t : g_P1);

        __syncthreads();   // prev iter's CS reads done
        for (int i = tid; i < 1024; i += 256) {
            int n = i >> 4, k4 = (i & 15) * 4;
            *(float4*)&BS(n, k4) = *(const float4*)&wT[(size_t)(h * 64 + n) * 64 + k4];
        }
        __syncthreads();

        float acc[4][4] = {};
#pragma unroll
        for (int kk = 0; kk < 8; kk++) {
#pragma unroll
            for (int t = 0; t < 4; t++) {
                uint32_t bf[2];
                load_bfr(Bs, n0 + t * 8 + grp, kk, qid, bf);
                mma_tf32(acc[t], afr[kk], bf);
            }
        }

        if (wsel == 0) {
#pragma unroll
            for (int t = 0; t < 4; t++) {
                int c = n0 + t * 8 + 2 * qid;
                float bv0 = bias[h * 64 + c], bv1 = bias[h * 64 + c + 1];
                CS(r0l, c)     = tf32f(fmaxf(acc[t][0] + bv0, 0.f));
                CS(r0l, c + 1) = tf32f(fmaxf(acc[t][1] + bv1, 0.f));
                CS(r1l, c)     = tf32f(fmaxf(acc[t][2] + bv0, 0.f));
                CS(r1l, c + 1) = tf32f(fmaxf(acc[t][3] + bv1, 0.f));
            }
            __syncthreads();
            for (int i = tid; i < 1024; i += 256) {
                int r = i >> 4, c4 = (i & 15) * 4;
                *(float4*)&outp[(((size_t)b * cH + h) * N + nbase + r) * 64 + c4] =
                    *(float4*)&CS(r, c4);
            }
        } else {
#pragma unroll
            for (int t = 0; t < 4; t++) {
                int c = n0 + t * 8 + 2 * qid;
                float bv0 = bias[h * 64 + c], bv1 = bias[h * 64 + c + 1];
                CS(c, r0l)     = tf32f(fmaxf(acc[t][0] + bv0, 0.f));
                CS(c + 1, r0l) = tf32f(fmaxf(acc[t][1] + bv1, 0.f));
                CS(c, r1l)     = tf32f(fmaxf(acc[t][2] + bv0, 0.f));
                CS(c + 1, r1l) = tf32f(fmaxf(acc[t][3] + bv1, 0.f));
            }
            __syncthreads();
            for (int i = tid; i < 1024; i += 256) {
                int d = i >> 4, r4 = (i & 15) * 4;
                *(float4*)&outp[(((size_t)b * cH + h) * 64 + d) * N + nbase + r4] =
                    *(float4*)&CS(d, r4);
            }
        }
    }
}

// =====================================================================
// energy_av: pass 1 = rowmax; pass 2 = recompute -> e -> g_att (coalesced)
// AND fused av MMA (e @ P2t) -> l3h. One launch replaces energy + av.
// =====================================================================
__global__ __launch_bounds__(256) void energy_av(const float* __restrict__ dist) {
    __shared__ float As[64 * 68];    // A tile, then CS e-stage
    __shared__ float Bs[64 * 68];    // P1 tile, then P2 tile
    __shared__ float red2[2][64];
    __shared__ float rowarr[64];
    const int bh = blockIdx.y, b = bh >> 3, h = bh & 7;
    const int l0 = blockIdx.x * 64;
    const int tid = threadIdx.x, wid = tid >> 5, lane = tid & 31, grp = lane >> 2, qid = lane & 3;
    const int mtw = wid & 3, nw = wid >> 2, m0 = mtw * 16, n0 = nw * 32;

    const float* Ag = g_L1 + ((size_t)bh * cNL + l0) * 64;
    for (int i = tid; i < 1024; i += 256) {
        int r = i >> 4, c4 = (i & 15) * 4;
        *(float4*)&AS(r, c4) = *(const float4*)&Ag[(size_t)r * 64 + c4];
    }
    __syncthreads();
    uint32_t afr[8][4];
#pragma unroll
    for (int kk = 0; kk < 8; kk++) load_afr(As, m0, grp, qid, kk, afr[kk]);

    const float* Bbase = g_P1 + (size_t)bh * cNP * 64;
    const float* P2b = g_P2t + (size_t)bh * 64 * cNP;
    float* ebase = g_att + ((size_t)bh * cNL + l0) * cNP;
    const int lm0 = m0 + grp, lm1 = lm0 + 8;
    const size_t drow0 = ((size_t)(b * cNL) + l0 + lm0) * cNP;
    const size_t drow1 = ((size_t)(b * cNL) + l0 + lm1) * cNP;
    const float hf = (float)h;

    // ---- pass 1: row max ----
    float mx0 = 0.f, mx1 = 0.f;      // masked entries carry logit 0
    for (int pt = 0; pt < 32; pt++) {
        const int p0 = pt * 64;
        __syncthreads();
        for (int i = tid; i < 1024; i += 256) {
            int p = i >> 4, k4 = (i & 15) * 4;
            *(float4*)&BS(p, k4) = *(const float4*)&Bbase[(size_t)(p0 + p) * 64 + k4];
        }
        __syncthreads();
        float acc[4][4] = {};
#pragma unroll
        for (int kk = 0; kk < 8; kk++)
#pragma unroll
            for (int t = 0; t < 4; t++) {
                uint32_t bf[2];
                load_bfr(Bs, n0 + t * 8 + grp, kk, qid, bf);
                mma_tf32(acc[t], afr[kk], bf);
            }
#pragma unroll
        for (int t = 0; t < 4; t++) {
            const int c = p0 + n0 + t * 8 + 2 * qid;
            const float2 dv0 = *(const float2*)&dist[drow0 + c];
            const float2 dv1 = *(const float2*)&dist[drow1 + c];
            const float dd[4] = {dv0.x, dv0.y, dv1.x, dv1.y};
#pragma unroll
            for (int j = 0; j < 4; j++) {
                const float d = dd[j];
                const bool m = (h < 7) ? (d > hf && d <= hf + 3.0f) : (d > 7.0f);
                const float inter = m ? __fdividef(1.0f, d) : 0.0f;
                const float lg = acc[t][j] * 0.125f * inter;
                if (j < 2) mx0 = fmaxf(mx0, lg); else mx1 = fmaxf(mx1, lg);
            }
        }
    }
    mx0 = fmaxf(mx0, __shfl_xor_sync(0xffffffffu, mx0, 1));
    mx0 = fmaxf(mx0, __shfl_xor_sync(0xffffffffu, mx0, 2));
    mx1 = fmaxf(mx1, __shfl_xor_sync(0xffffffffu, mx1, 1));
    mx1 = fmaxf(mx1, __shfl_xor_sync(0xffffffffu, mx1, 2));
    if (qid == 0) { red2[nw][lm0] = mx0; red2[nw][lm1] = mx1; }
    __syncthreads();
    if (tid < 64) rowarr[tid] = fmaxf(red2[0][tid], red2[1][tid]);
    __syncthreads();
    const float rm0 = rowarr[lm0], rm1 = rowarr[lm1];

    // ---- pass 2: e -> g_att + fused av ----
    float rs0 = 0.f, rs1 = 0.f;
    float accv[4][4] = {};
    for (int pt = 0; pt < 32; pt++) {
        const int p0 = pt * 64;
        __syncthreads();                                 // S1: prev iter fully done
        for (int i = tid; i < 1024; i += 256) {
            int p = i >> 4, k4 = (i & 15) * 4;
            *(float4*)&BS(p, k4) = *(const float4*)&Bbase[(size_t)(p0 + p) * 64 + k4];
        }
        __syncthreads();                                 // S2
        float acc[4][4] = {};
#pragma unroll
        for (int kk = 0; kk < 8; kk++)
#pragma unroll
            for (int t = 0; t < 4; t++) {
                uint32_t bf[2];
                load_bfr(Bs, n0 + t * 8 + grp, kk, qid, bf);
                mma_tf32(acc[t], afr[kk], bf);
            }
#pragma unroll
        for (int t = 0; t < 4; t++) {
            const int c = p0 + n0 + t * 8 + 2 * qid;
            const float2 dv0 = *(const float2*)&dist[drow0 + c];
            const float2 dv1 = *(const float2*)&dist[drow1 + c];
            const float dd[4] = {dv0.x, dv0.y, dv1.x, dv1.y};
            float ev[4];
#pragma unroll
            for (int j = 0; j < 4; j++) {
                const float d = dd[j];
                const bool m = (h < 7) ? (d > hf && d <= hf + 3.0f) : (d > 7.0f);
                const float inter = m ? __fdividef(1.0f, d) : 0.0f;
                const float lg = acc[t][j] * 0.125f * inter;
                ev[j] = __expf(lg - (j < 2 ? rm0 : rm1));
            }
            rs0 += ev[0] + ev[1];
            rs1 += ev[2] + ev[3];
            const int cl = n0 + t * 8 + 2 * qid;
            CS(lm0, cl)     = tf32f(ev[0]);
            CS(lm0, cl + 1) = tf32f(ev[1]);
            CS(lm1, cl)     = tf32f(ev[2]);
            CS(lm1, cl + 1) = tf32f(ev[3]);
        }
        __syncthreads();                                 // S3: CS ready, Bs(P1) reads done
        for (int i = tid; i < 1024; i += 256) {          // P2 tile -> Bs
            int d = i >> 4, p4 = (i & 15) * 4;
            *(float4*)&BS(d, p4) = *(const float4*)&P2b[(size_t)d * cNP + p0 + p4];
        }
        for (int i = tid; i < 1024; i += 256) {          // coalesced g_att write
            int l = i >> 4, c4 = (i & 15) * 4;
            *(float4*)&ebase[(size_t)l * cNP + p0 + c4] = *(float4*)&CS(l, c4);
        }
        __syncthreads();                                 // S4: Bs(P2) ready
        // av MMA: A = e tile (CS), B = P2 tile (Bs)
#pragma unroll
        for (int kk = 0; kk < 8; kk++) {
            uint32_t a[4];
            load_afr(As, m0, grp, qid, kk, a);
#pragma unroll
            for (int t = 0; t < 4; t++) {
                uint32_t bf[2];
                load_bfr(Bs, n0 + t * 8 + grp, kk, qid, bf);
                mma_tf32(accv[t], a, bf);
            }
        }
    }

    rs0 += __shfl_xor_sync(0xffffffffu, rs0, 1);
    rs0 += __shfl_xor_sync(0xffffffffu, rs0, 2);
    rs1 += __shfl_xor_sync(0xffffffffu, rs1, 1);
    rs1 += __shfl_xor_sync(0xffffffffu, rs1, 2);
    __syncthreads();   // also guards CS reuse below (av MMA reads done)
    if (qid == 0) { red2[nw][lm0] = rs0; red2[nw][lm1] = rs1; }
    __syncthreads();
    if (tid < 64) {
        float inv = 1.0f / (red2[0][tid] + red2[1][tid]);
        rowarr[tid] = inv;
        g_sinv[bh * cNL + l0 + tid] = inv;
    }
    __syncthreads();
    const float inv0 = rowarr[lm0], inv1 = rowarr[lm1];
#pragma unroll
    for (int t = 0; t < 4; t++) {
        const int c = n0 + t * 8 + 2 * qid;
        CS(lm0, c)     = tf32f(accv[t][0] * inv0);
        CS(lm0, c + 1) = tf32f(accv[t][1] * inv0);
        CS(lm1, c)     = tf32f(accv[t][2] * inv1);
        CS(lm1, c + 1) = tf32f(accv[t][3] * inv1);
    }
    __syncthreads();
    for (int i = tid; i < 1024; i += 256) {
        int l = i >> 4, c4 = (i & 15) * 4;
        *(float4*)&g_l3h[((size_t)(b * cNL) + l0 + l) * 512 + h * 64 + c4] =
            *(float4*)&CS(l, c4);
    }
}

// =====================================================================
// atv: p3h[b,p,h*64+d] = sum_l e[l,p] * (L2t[d,l] * sinv[l]).
// Block = 128 p x 64 d, K = 256 in tiles of 32; stride-36 smem.
// =====================================================================
__global__ __launch_bounds__(256) void atv_mma() {
    __shared__ float Ae[128 * 36];   // e^T [p][l]
    __shared__ float Bl[64 * 36];    // scaled L2t [d][l]
#define ATS(p_, c_) Ae[(p_) * 68 + (c_)]   // epilogue stage overlays Ae (4352<4608)
    const int bh = blockIdx.y, b = bh >> 3, h = bh & 7;
    const int p0 = blockIdx.x * 128;
    const int tid = threadIdx.x, wid = tid >> 5, lane = tid & 31, grp = lane >> 2, qid = lane & 3;
    const int m0 = wid * 16;
    const float* eb = g_att + (size_t)bh * cNL * cNP;
    const float* L2b = g_L2t + (size_t)bh * 64 * cNL;
    const float* sv = g_sinv + (size_t)bh * cNL;
    float acc[8][4] = {};

    for (int lt = 0; lt < 8; lt++) {
        const int lb = lt * 32;
        __syncthreads();
        for (int i = tid; i < 4096; i += 256) {
            int r = i >> 7, c = i & 127;    // r = l local, c = p local
            Ae[c * 36 + r] = eb[(size_t)(lb + r) * cNP + p0 + c];
        }
        for (int i = tid; i < 2048; i += 256) {
            int d = i >> 5, k = i & 31;
            Bl[d * 36 + k] = tf32f(L2b[(size_t)d * cNL + lb + k] * sv[lb + k]);
        }
        __syncthreads();
#pragma unroll
        for (int kk = 0; kk < 4; kk++) {
            const int k0 = kk * 8;
            uint32_t a[4] = { __float_as_uint(Ae[(m0 + grp) * 36 + k0 + qid]),
                              __float_as_uint(Ae[(m0 + grp + 8) * 36 + k0 + qid]),
                              __float_as_uint(Ae[(m0 + grp) * 36 + k0 + qid + 4]),
                              __float_as_uint(Ae[(m0 + grp + 8) * 36 + k0 + qid + 4]) };
#pragma unroll
            for (int t = 0; t < 8; t++) {
                uint32_t bf[2] = { __float_as_uint(Bl[(t * 8 + grp) * 36 + k0 + qid]),
                                   __float_as_uint(Bl[(t * 8 + grp) * 36 + k0 + qid + 4]) };
                mma_tf32(acc[t], a, bf);
            }
        }
    }

#pragma unroll
    for (int half = 0; half < 2; half++) {
        __syncthreads();
        if ((wid >> 2) == half) {
            const int pl0 = (m0 & 63) + grp, pl1 = pl0 + 8;
#pragma unroll
            for (int t = 0; t < 8; t++) {
                const int c = t * 8 + 2 * qid;
                ATS(pl0, c)     = tf32f(acc[t][0]);
                ATS(pl0, c + 1) = tf32f(acc[t][1]);
                ATS(pl1, c)     = tf32f(acc[t][2]);
                ATS(pl1, c + 1) = tf32f(acc[t][3]);
            }
        }
        __syncthreads();
        const int pg = p0 + half * 64;
        for (int i = tid; i < 1024; i += 256) {
            int pl = i >> 4, c4 = (i & 15) * 4;
            *(float4*)&g_p3h[((size_t)(b * cNP) + pg + pl) * 512 + h * 64 + c4] =
                *(float4*)&ATS(pl, c4);
        }
    }
#undef ATS
}

// =====================================================================
// fc_fused: Y1 = X @ W1 + b1 (no relu); out = relu([Y1, orig] @ W2 + b2).
// Y1 never leaves smem.
// =====================================================================
__global__ __launch_bounds__(256) void fc_fused(const float* __restrict__ orig,
                                                const float* __restrict__ b1,
                                                const float* __restrict__ b2,
                                                float* __restrict__ out,
                                                int N, int which, int row_off) {
    const float* X = which ? g_p3h : g_l3h;
    const float* W1 = g_f1T[which];
    const float* W2 = g_f2T[which];
    __shared__ float As[64 * 68];
    __shared__ float Bs[64 * 68];
    const int row0 = blockIdx.x * 64;
    const int tid = threadIdx.x, wid = tid >> 5, lane = tid & 31, grp = lane >> 2, qid = lane & 3;
    const int mtw = wid & 3, nw = wid >> 2, m0 = mtw * 16, n0 = nw * 32;
    const int r0l = m0 + grp, r1l = r0l + 8;

    // ---- fc1 ----
    float acc[4][4] = {};
    for (int kt = 0; kt < 8; kt++) {
        const int kb = kt * 64;
        __syncthreads();
        for (int i = tid; i < 1024; i += 256) {
            int r = i >> 4, k4 = (i & 15) * 4;
            *(float4*)&AS(r, k4) = *(const float4*)&X[(size_t)(row0 + r) * 512 + kb + k4];
        }
        for (int i = tid; i < 1024; i += 256) {
            int n = i >> 4, k4 = (i & 15) * 4;
            *(float4*)&BS(n, k4) = *(const float4*)&W1[(size_t)n * 512 + kb + k4];
        }
        __syncthreads();
#pragma unroll
        for (int kk = 0; kk < 8; kk++) {
            uint32_t a[4];
            load_afr(As, m0, grp, qid, kk, a);
#pragma unroll
            for (int t = 0; t < 4; t++) {
                uint32_t bf[2];
                load_bfr(Bs, n0 + t * 8 + grp, kk, qid, bf);
                mma_tf32(acc[t], a, bf);
            }
        }
    }
    __syncthreads();
    // stage Y1 (tf32, no relu) into CS; load W2 kt0 tile
#pragma unroll
    for (int t = 0; t < 4; t++) {
        const int c = n0 + t * 8 + 2 * qid;
        const float bv0 = b1[c], bv1 = b1[c + 1];
        CS(r0l, c)     = tf32f(acc[t][0] + bv0);
        CS(r0l, c + 1) = tf32f(acc[t][1] + bv1);
        CS(r1l, c)     = tf32f(acc[t][2] + bv0);
        CS(r1l, c + 1) = tf32f(acc[t][3] + bv1);
    }
    for (int i = tid; i < 1024; i += 256) {
        int n = i >> 4, k4 = (i & 15) * 4;
        *(float4*)&BS(n, k4) = *(const float4*)&W2[(size_t)n * 128 + k4];
    }
    __syncthreads();

    // ---- fc2, kt0 (Y1) ----
    float acc2[4][4] = {};
#pragma unroll
    for (int kk = 0; kk < 8; kk++) {
        uint32_t a[4];
        load_afr(As, m0, grp, qid, kk, a);
#pragma unroll
        for (int t = 0; t < 4; t++) {
            uint32_t bf[2];
            load_bfr(Bs, n0 + t * 8 + grp, kk, qid, bf);
            mma_tf32(acc2[t], a, bf);
        }
    }
    __syncthreads();
    // ---- fc2, kt1 (orig) ----
    for (int i = tid; i < 1024; i += 256) {
        int r = i >> 4, c4 = (i & 15) * 4;
        float4 v = *(const float4*)&orig[(size_t)(row0 + r) * 64 + c4];
        v.x = tf32f(v.x); v.y = tf32f(v.y); v.z = tf32f(v.z); v.w = tf32f(v.w);
        *(float4*)&AS(r, c4) = v;
    }
    for (int i = tid; i < 1024; i += 256) {
        int n = i >> 4, k4 = (i & 15) * 4;
        *(float4*)&BS(n, k4) = *(const float4*)&W2[(size_t)n * 128 + 64 + k4];
    }
    __syncthreads();
#pragma unroll
    for (int kk = 0; kk < 8; kk++) {
        uint32_t a[4];
        load_afr(As, m0, grp, qid, kk, a);
#pragma unroll
        for (int t = 0; t < 4; t++) {
            uint32_t bf[2];
            load_bfr(Bs, n0 + t * 8 + grp, kk, qid, bf);
            mma_tf32(acc2[t], a, bf);
        }
    }
    __syncthreads();
    // epilogue
#pragma unroll
    for (int t = 0; t < 4; t++) {
        const int c = n0 + t * 8 + 2 * qid;
        const float bv0 = b2[c], bv1 = b2[c + 1];
        CS(r0l, c)     = fmaxf(acc2[t][0] + bv0, 0.f);
        CS(r0l, c + 1) = fmaxf(acc2[t][1] + bv1, 0.f);
        CS(r1l, c)     = fmaxf(acc2[t][2] + bv0, 0.f);
        CS(r1l, c + 1) = fmaxf(acc2[t][3] + bv1, 0.f);
    }
    __syncthreads();
    const int b = row0 / N, nbase = row0 % N;
    for (int i = tid; i < 1024; i += 256) {
        int r = i >> 4, c4 = (i & 15) * 4;
        *(float4*)&out[((size_t)b * cNT + row_off + nbase + r) * 64 + c4] =
            *(float4*)&CS(r, c4);
    }
}

// =====================================================================
extern "C" void kernel_launch(void* const* d_in, const int* in_sizes, int n_in,
                              void* d_out, int out_size) {
    (void)in_sizes; (void)n_in; (void)out_size;
    const float* ligand = (const float*)d_in[0];
    const float* prot   = (const float*)d_in[1];
    const float* dist   = (const float*)d_in[2];
    const float* w_l1 = (const float*)d_in[3];
    const float* b_l1 = (const float*)d_in[4];
    const float* w_l2 = (const float*)d_in[5];
    const float* b_l2 = (const float*)d_in[6];
    const float* w_p1 = (const float*)d_in[7];
    const float* b_p1 = (const float*)d_in[8];
    const float* w_p2 = (const float*)d_in[9];
    const float* b_p2 = (const float*)d_in[10];
    const float* fc11_w = (const float*)d_in[11];
    const float* fc11_b = (const float*)d_in[12];
    const float* fc12_w = (const float*)d_in[13];
    const float* fc12_b = (const float*)d_in[14];
    const float* fc21_w = (const float*)d_in[15];
    const float* fc21_b = (const float*)d_in[16];
    const float* fc22_w = (const float*)d_in[17];
    const float* fc22_b = (const float*)d_in[18];
    float* out = (float*)d_out;

    prep_weights<<<832, 256>>>(w_l1, w_l2, w_p1, w_p2, fc11_w, fc21_w, fc12_w, fc22_w);
    proj2<<<cB * cNL / 64, 256>>>(ligand, b_l1, b_l2, cNL, 0);
    proj2<<<cB * cNP / 64, 256>>>(prot, b_p1, b_p2, cNP, 1);
    energy_av<<<dim3(cNL / 64, cB * cH), 256>>>(dist);
    atv_mma<<<dim3(cNP / 128, cB * cH), 256>>>();
    fc_fused<<<cB * cNL / 64, 256>>>(ligand, fc11_b, fc12_b, out, cNL, 0, 0);
    fc_fused<<<cB * cNP / 64, 256>>>(prot, fc21_b, fc22_b, out, cNP, 1, cNL);
}

// round 7
// speedup vs baseline: 1.2677x; 1.2024x over previous
#include <cuda_runtime.h>
#include <math.h>
#include <stdint.h>

// Problem constants
constexpr int cB  = 16;
constexpr int cH  = 8;
constexpr int cNL = 256;
constexpr int cNP = 2048;
constexpr int cD  = 64;          // HID
constexpr int cNT = cNL + cNP;   // 2304

// ---------------- scratch (device globals; no runtime allocation) ----------------
__device__ float g_L1 [cB * cH * cNL * cD];         // [bh][l][d]   (tf32, relu)
__device__ float g_L2t[cB * cH * cD * cNL];         // [bh][d][l]
__device__ float g_P1 [cB * cH * cNP * cD];         // [bh][p][d]
__device__ float g_P2t[cB * cH * cD * cNP];         // [bh][d][p]
__device__ float g_att[(size_t)cB * cH * cNL * cNP];// e at historical max scale, tf32
__device__ float g_mthen[cB * cH * 32 * cNL];       // [bh][pt][l] running max at tile pt
__device__ float g_sinv[cB * cH * cNL];             // 1 / row-sum of e (final scale)
__device__ float g_l3h[cB * cNL * cH * cD];         // [B, Nl, 512] (tf32)
__device__ float g_p3h[cB * cNP * cH * cD];         // [B, Np, 512] (tf32)
// transposed + tf32-rounded weights
__device__ float g_wT [4][512 * 64];                // proj: [(h*64+n)][k]
__device__ float g_f1T[2][64 * 512];                // fc11/fc21: [n][k]
__device__ float g_f2T[2][64 * 128];                // fc12/fc22: [n][k]

// ---------------- tf32 helpers ----------------
__device__ __forceinline__ float tf32f(float x) {
    uint32_t u;
    asm("cvt.rna.tf32.f32 %0, %1;" : "=r"(u) : "f"(x));
    return __uint_as_float(u);
}

__device__ __forceinline__ void mma_tf32(float d[4], const uint32_t a[4], const uint32_t b[2]) {
    asm volatile(
        "mma.sync.aligned.m16n8k8.row.col.f32.tf32.tf32.f32 "
        "{%0,%1,%2,%3}, {%4,%5,%6,%7}, {%8,%9}, {%0,%1,%2,%3};\n"
        : "+f"(d[0]), "+f"(d[1]), "+f"(d[2]), "+f"(d[3])
        : "r"(a[0]), "r"(a[1]), "r"(a[2]), "r"(a[3]), "r"(b[0]), "r"(b[1]));
}

#define AS(r_, c_) As[(r_) * 68 + (c_)]
#define BS(r_, c_) Bs[(r_) * 68 + (c_)]
#define CS(r_, c_) As[(r_) * 68 + (c_)]   // stage aliases As region

__device__ __forceinline__ void load_afr(const float* As_, int m0, int grp, int qid,
                                         int kk, uint32_t a[4]) {
    const int k0 = kk * 8;
    a[0] = __float_as_uint(As_[(m0 + grp) * 68 + k0 + qid]);
    a[1] = __float_as_uint(As_[(m0 + grp + 8) * 68 + k0 + qid]);
    a[2] = __float_as_uint(As_[(m0 + grp) * 68 + k0 + qid + 4]);
    a[3] = __float_as_uint(As_[(m0 + grp + 8) * 68 + k0 + qid + 4]);
}

__device__ __forceinline__ void load_bfr(const float* Bs_, int n, int kk, int qid,
                                         uint32_t b[2]) {
    const int k0 = kk * 8;
    b[0] = __float_as_uint(Bs_[n * 68 + k0 + qid]);
    b[1] = __float_as_uint(Bs_[n * 68 + k0 + qid + 4]);
}

// =====================================================================
// prep: transpose + tf32-round all weights once.
// =====================================================================
__global__ __launch_bounds__(256) void prep_weights(
    const float* __restrict__ wl1, const float* __restrict__ wl2,
    const float* __restrict__ wp1, const float* __restrict__ wp2,
    const float* __restrict__ f11, const float* __restrict__ f21,
    const float* __restrict__ f12, const float* __restrict__ f22) {
    int i = blockIdx.x * 256 + threadIdx.x;
    if (i < 4 * 32768) {
        int w = i >> 15, r = i & 32767;          // r = hn*64 + k
        int hn = r >> 6, k = r & 63;
        const float* src = (w == 0) ? wl1 : (w == 1) ? wl2 : (w == 2) ? wp1 : wp2;
        g_wT[w][r] = tf32f(src[(size_t)k * 512 + hn]);
    } else if (i < 6 * 32768) {
        int j = i - 4 * 32768;
        int w = j >> 15, r = j & 32767;          // r = n*512 + k
        int n = r >> 9, k = r & 511;
        const float* src = w ? f21 : f11;
        g_f1T[w][r] = tf32f(src[(size_t)k * 64 + n]);
    } else if (i < 6 * 32768 + 2 * 8192) {
        int j = i - 6 * 32768;
        int w = j >> 13, r = j & 8191;           // r = n*128 + k
        int n = r >> 7, k = r & 127;
        const float* src = w ? f22 : f12;
        g_f2T[w][r] = tf32f(src[(size_t)k * 64 + n]);
    }
}

// =====================================================================
// proj2: both projections for one input. Block = 64 rows; x tile loaded once,
// A-fragments hoisted; loop over 16 (weight, head) B-tiles.
// =====================================================================
__global__ __launch_bounds__(256) void proj2(const float* __restrict__ x,
                                             const float* __restrict__ bA,
                                             const float* __restrict__ bB,
                                             int N, int which) {
    __shared__ float As[64 * 68];
    __shared__ float Bs[64 * 68];
    const int row0 = blockIdx.x * 64;
    const int tid = threadIdx.x;

    for (int i = tid; i < 1024; i += 256) {
        int r = i >> 4, c4 = (i & 15) * 4;
        float4 v = *(const float4*)&x[(size_t)(row0 + r) * 64 + c4];
        v.x = tf32f(v.x); v.y = tf32f(v.y); v.z = tf32f(v.z); v.w = tf32f(v.w);
        *(float4*)&AS(r, c4) = v;
    }
    __syncthreads();

    const int wid = tid >> 5, lane = tid & 31, grp = lane >> 2, qid = lane & 3;
    const int mtw = wid & 3, nw = wid >> 2;
    const int m0 = mtw * 16, n0 = nw * 32;
    uint32_t afr[8][4];
#pragma unroll
    for (int kk = 0; kk < 8; kk++) load_afr(As, m0, grp, qid, kk, afr[kk]);

    const int b = row0 / N, nbase = row0 % N;
    const int r0l = m0 + grp, r1l = r0l + 8;

    for (int it = 0; it < 16; it++) {
        const int wsel = it >> 3, h = it & 7;
        const float* wT = g_wT[which * 2 + wsel];
        const float* bias = wsel ? bB : bA;
        float* outp = (which == 0) ? (wsel ? g_L2t : g_L1) : (wsel ? g_P2t : g_P1);

        __syncthreads();   // prev iter's CS reads done
        for (int i = tid; i < 1024; i += 256) {
            int n = i >> 4, k4 = (i & 15) * 4;
            *(float4*)&BS(n, k4) = *(const float4*)&wT[(size_t)(h * 64 + n) * 64 + k4];
        }
        __syncthreads();

        float acc[4][4] = {};
#pragma unroll
        for (int kk = 0; kk < 8; kk++) {
#pragma unroll
            for (int t = 0; t < 4; t++) {
                uint32_t bf[2];
                load_bfr(Bs, n0 + t * 8 + grp, kk, qid, bf);
                mma_tf32(acc[t], afr[kk], bf);
            }
        }

        if (wsel == 0) {
#pragma unroll
            for (int t = 0; t < 4; t++) {
                int c = n0 + t * 8 + 2 * qid;
                float bv0 = bias[h * 64 + c], bv1 = bias[h * 64 + c + 1];
                CS(r0l, c)     = tf32f(fmaxf(acc[t][0] + bv0, 0.f));
                CS(r0l, c + 1) = tf32f(fmaxf(acc[t][1] + bv1, 0.f));
                CS(r1l, c)     = tf32f(fmaxf(acc[t][2] + bv0, 0.f));
                CS(r1l, c + 1) = tf32f(fmaxf(acc[t][3] + bv1, 0.f));
            }
            __syncthreads();
            for (int i = tid; i < 1024; i += 256) {
                int r = i >> 4, c4 = (i & 15) * 4;
                *(float4*)&outp[(((size_t)b * cH + h) * N + nbase + r) * 64 + c4] =
                    *(float4*)&CS(r, c4);
            }
        } else {
#pragma unroll
            for (int t = 0; t < 4; t++) {
                int c = n0 + t * 8 + 2 * qid;
                float bv0 = bias[h * 64 + c], bv1 = bias[h * 64 + c + 1];
                CS(c, r0l)     = tf32f(fmaxf(acc[t][0] + bv0, 0.f));
                CS(c + 1, r0l) = tf32f(fmaxf(acc[t][1] + bv1, 0.f));
                CS(c, r1l)     = tf32f(fmaxf(acc[t][2] + bv0, 0.f));
                CS(c + 1, r1l) = tf32f(fmaxf(acc[t][3] + bv1, 0.f));
            }
            __syncthreads();
            for (int i = tid; i < 1024; i += 256) {
                int d = i >> 4, r4 = (i & 15) * 4;
                *(float4*)&outp[(((size_t)b * cH + h) * 64 + d) * N + nbase + r4] =
                    *(float4*)&CS(d, r4);
            }
        }
    }
}

// =====================================================================
// energy_av: ONLINE softmax, single pass over p. Block = 32 l rows, 1024 blocks.
// Per tile: energy MMA -> logits -> running rowmax -> e (historical scale) to
// g_att + m_then; fused av MMA with accumulator rescale. sinv at end.
// =====================================================================
__global__ void __launch_bounds__(256, 3) energy_av(const float* __restrict__ dist) {
    __shared__ float As[32 * 68];        // L1 tile, then e-stage (CS)
    __shared__ float Bs[64 * 68];        // P1 tile / P2 tile
    __shared__ float tm[4][32];
    __shared__ float red[4][32];
    const int bh = blockIdx.y, b = bh >> 3, h = bh & 7;
    const int l0 = blockIdx.x * 32;
    const int tid = threadIdx.x, wid = tid >> 5, lane = tid & 31;
    const int grp = lane >> 2, qid = lane & 3;
    const int mtw = wid & 1, nw = wid >> 1;          // 2 m-warps x 4 n-warps
    const int m0 = mtw * 16, n0 = nw * 16;

    const float* Ag = g_L1 + ((size_t)bh * cNL + l0) * 64;
    for (int i = tid; i < 512; i += 256) {
        int r = i >> 4, c4 = (i & 15) * 4;
        *(float4*)&AS(r, c4) = *(const float4*)&Ag[(size_t)r * 64 + c4];
    }
    __syncthreads();
    uint32_t afr[8][4];
#pragma unroll
    for (int kk = 0; kk < 8; kk++) load_afr(As, m0, grp, qid, kk, afr[kk]);
    __syncthreads();   // As free for CS reuse

    const float* Bbase = g_P1 + (size_t)bh * cNP * 64;
    const float* P2b = g_P2t + (size_t)bh * 64 * cNP;
    float* ebase = g_att + ((size_t)bh * cNL + l0) * cNP;
    const int lm0 = m0 + grp, lm1 = lm0 + 8;
    const size_t drow0 = ((size_t)(b * cNL) + l0 + lm0) * cNP;
    const size_t drow1 = ((size_t)(b * cNL) + l0 + lm1) * cNP;
    const float hf = (float)h;

    float mold0 = 0.f, mold1 = 0.f, s0 = 0.f, s1 = 0.f;  // masked logits are 0 -> max >= 0
    float accv[2][4] = {};

    for (int pt = 0; pt < 32; pt++) {
        const int p0 = pt * 64;
        __syncthreads();                               // S_A: prev av MMA done
        float2 dv0[2], dv1[2];
#pragma unroll
        for (int t = 0; t < 2; t++) {
            const int c = p0 + n0 + t * 8 + 2 * qid;
            dv0[t] = *(const float2*)&dist[drow0 + c];
            dv1[t] = *(const float2*)&dist[drow1 + c];
        }
        for (int i = tid; i < 1024; i += 256) {
            int p = i >> 4, k4 = (i & 15) * 4;
            *(float4*)&BS(p, k4) = *(const float4*)&Bbase[(size_t)(p0 + p) * 64 + k4];
        }
        __syncthreads();                               // S_B: P1 ready
        float acc[2][4] = {};
#pragma unroll
        for (int kk = 0; kk < 8; kk++)
#pragma unroll
            for (int t = 0; t < 2; t++) {
                uint32_t bf[2];
                load_bfr(Bs, n0 + t * 8 + grp, kk, qid, bf);
                mma_tf32(acc[t], afr[kk], bf);
            }
        float lg[2][4];
#pragma unroll
        for (int t = 0; t < 2; t++) {
            const float dd[4] = {dv0[t].x, dv0[t].y, dv1[t].x, dv1[t].y};
#pragma unroll
            for (int j = 0; j < 4; j++) {
                const float d = dd[j];
                const bool msk = (h < 7) ? (d > hf && d <= hf + 3.0f) : (d > 7.0f);
                const float inter = msk ? __fdividef(1.0f, d) : 0.0f;
                lg[t][j] = acc[t][j] * 0.125f * inter;
            }
        }
        float tx0 = fmaxf(fmaxf(lg[0][0], lg[0][1]), fmaxf(lg[1][0], lg[1][1]));
        float tx1 = fmaxf(fmaxf(lg[0][2], lg[0][3]), fmaxf(lg[1][2], lg[1][3]));
        tx0 = fmaxf(tx0, __shfl_xor_sync(0xffffffffu, tx0, 1));
        tx0 = fmaxf(tx0, __shfl_xor_sync(0xffffffffu, tx0, 2));
        tx1 = fmaxf(tx1, __shfl_xor_sync(0xffffffffu, tx1, 1));
        tx1 = fmaxf(tx1, __shfl_xor_sync(0xffffffffu, tx1, 2));
        if (qid == 0) { tm[nw][lm0] = tx0; tm[nw][lm1] = tx1; }
        __syncthreads();                               // S_C: tile maxima visible
        const float mn0 = fmaxf(fmaxf(fmaxf(tm[0][lm0], tm[1][lm0]),
                                      fmaxf(tm[2][lm0], tm[3][lm0])), mold0);
        const float mn1 = fmaxf(fmaxf(fmaxf(tm[0][lm1], tm[1][lm1]),
                                      fmaxf(tm[2][lm1], tm[3][lm1])), mold1);
        const float f0 = __expf(mold0 - mn0), f1 = __expf(mold1 - mn1);
        mold0 = mn0; mold1 = mn1;
        float ps0 = 0.f, ps1 = 0.f;
#pragma unroll
        for (int t = 0; t < 2; t++) {
            float e0 = __expf(lg[t][0] - mn0), e1 = __expf(lg[t][1] - mn0);
            float e2 = __expf(lg[t][2] - mn1), e3 = __expf(lg[t][3] - mn1);
            ps0 += e0 + e1; ps1 += e2 + e3;
            const int c = n0 + t * 8 + 2 * qid;
            CS(lm0, c)     = tf32f(e0); CS(lm0, c + 1) = tf32f(e1);
            CS(lm1, c)     = tf32f(e2); CS(lm1, c + 1) = tf32f(e3);
            accv[t][0] *= f0; accv[t][1] *= f0; accv[t][2] *= f1; accv[t][3] *= f1;
        }
        s0 = s0 * f0 + ps0; s1 = s1 * f1 + ps1;
        if (qid == 0 && nw == 0) {
            g_mthen[((size_t)bh * 32 + pt) * cNL + l0 + lm0] = mn0;
            g_mthen[((size_t)bh * 32 + pt) * cNL + l0 + lm1] = mn1;
        }
        __syncthreads();                               // S_D: CS staged, P1 reads done
        for (int i = tid; i < 1024; i += 256) {        // P2 tile -> Bs
            int dd_ = i >> 4, p4 = (i & 15) * 4;
            *(float4*)&BS(dd_, p4) = *(const float4*)&P2b[(size_t)dd_ * cNP + p0 + p4];
        }
        for (int i = tid; i < 512; i += 256) {         // coalesced g_att write
            int l = i >> 4, c4 = (i & 15) * 4;
            *(float4*)&ebase[(size_t)l * cNP + p0 + c4] = *(float4*)&CS(l, c4);
        }
        __syncthreads();                               // S_E: P2 ready
#pragma unroll
        for (int kk = 0; kk < 8; kk++) {
            uint32_t a[4];
            load_afr(As, m0, grp, qid, kk, a);
#pragma unroll
            for (int t = 0; t < 2; t++) {
                uint32_t bf[2];
                load_bfr(Bs, n0 + t * 8 + grp, kk, qid, bf);
                mma_tf32(accv[t], a, bf);
            }
        }
    }

    // row sums -> sinv; accv already at final max scale
    s0 += __shfl_xor_sync(0xffffffffu, s0, 1); s0 += __shfl_xor_sync(0xffffffffu, s0, 2);
    s1 += __shfl_xor_sync(0xffffffffu, s1, 1); s1 += __shfl_xor_sync(0xffffffffu, s1, 2);
    if (qid == 0) { red[nw][lm0] = s0; red[nw][lm1] = s1; }
    __syncthreads();
    const float inv0 = 1.0f / (red[0][lm0] + red[1][lm0] + red[2][lm0] + red[3][lm0]);
    const float inv1 = 1.0f / (red[0][lm1] + red[1][lm1] + red[2][lm1] + red[3][lm1]);
    if (qid == 0 && nw == 0) {
        g_sinv[bh * cNL + l0 + lm0] = inv0;
        g_sinv[bh * cNL + l0 + lm1] = inv1;
    }
#pragma unroll
    for (int t = 0; t < 2; t++) {
        const int c = n0 + t * 8 + 2 * qid;
        CS(lm0, c)     = tf32f(accv[t][0] * inv0);
        CS(lm0, c + 1) = tf32f(accv[t][1] * inv0);
        CS(lm1, c)     = tf32f(accv[t][2] * inv1);
        CS(lm1, c + 1) = tf32f(accv[t][3] * inv1);
    }
    __syncthreads();
    for (int i = tid; i < 512; i += 256) {
        int l = i >> 4, c4 = (i & 15) * 4;
        *(float4*)&g_l3h[((size_t)(b * cNL) + l0 + l) * 512 + h * 64 + c4] =
            *(float4*)&CS(l, c4);
    }
}

// =====================================================================
// atv: p3h[b,p,h*64+d] = sum_l e[l,p]*cf[l,pt] * (L2t[d,l] * sinv[l]).
// cf[l,pt] = exp(m_then[pt][l] - m_final[l]) corrects historical e scale.
// =====================================================================
__global__ __launch_bounds__(256) void atv_mma() {
    __shared__ float Ae[128 * 36];   // e^T [p][l]
    __shared__ float Bl[64 * 36];    // scaled L2t [d][l]
    __shared__ float cfa[2][256];    // corrections for this block's 2 p-tiles
#define ATS(p_, c_) Ae[(p_) * 68 + (c_)]   // epilogue stage overlays Ae
    const int bh = blockIdx.y, b = bh >> 3, h = bh & 7;
    const int p0 = blockIdx.x * 128;
    const int tid = threadIdx.x, wid = tid >> 5, lane = tid & 31, grp = lane >> 2, qid = lane & 3;
    const int m0 = wid * 16;
    const float* eb = g_att + (size_t)bh * cNL * cNP;
    const float* L2b = g_L2t + (size_t)bh * 64 * cNL;
    const float* sv = g_sinv + (size_t)bh * cNL;
    const int pt0 = p0 >> 6;

    for (int i = tid; i < 512; i += 256) {
        int v = i >> 8, j = i & 255;
        float mf = g_mthen[((size_t)bh * 32 + 31) * cNL + j];
        float mt = g_mthen[((size_t)bh * 32 + pt0 + v) * cNL + j];
        cfa[v][j] = __expf(mt - mf);
    }

    float acc[8][4] = {};
    for (int lt = 0; lt < 8; lt++) {
        const int lb = lt * 32;
        __syncthreads();   // also guards cfa readiness on first iter
        for (int i = tid; i < 4096; i += 256) {
            int r = i >> 7, c = i & 127;    // r = l local, c = p local
            Ae[c * 36 + r] = tf32f(eb[(size_t)(lb + r) * cNP + p0 + c] * cfa[c >> 6][lb + r]);
        }
        for (int i = tid; i < 2048; i += 256) {
            int d = i >> 5, k = i & 31;
            Bl[d * 36 + k] = tf32f(L2b[(size_t)d * cNL + lb + k] * sv[lb + k]);
        }
        __syncthreads();
#pragma unroll
        for (int kk = 0; kk < 4; kk++) {
            const int k0 = kk * 8;
            uint32_t a[4] = { __float_as_uint(Ae[(m0 + grp) * 36 + k0 + qid]),
                              __float_as_uint(Ae[(m0 + grp + 8) * 36 + k0 + qid]),
                              __float_as_uint(Ae[(m0 + grp) * 36 + k0 + qid + 4]),
                              __float_as_uint(Ae[(m0 + grp + 8) * 36 + k0 + qid + 4]) };
#pragma unroll
            for (int t = 0; t < 8; t++) {
                uint32_t bf[2] = { __float_as_uint(Bl[(t * 8 + grp) * 36 + k0 + qid]),
                                   __float_as_uint(Bl[(t * 8 + grp) * 36 + k0 + qid + 4]) };
                mma_tf32(acc[t], a, bf);
            }
        }
    }

#pragma unroll
    for (int half = 0; half < 2; half++) {
        __syncthreads();
        if ((wid >> 2) == half) {
            const int pl0 = (m0 & 63) + grp, pl1 = pl0 + 8;
#pragma unroll
            for (int t = 0; t < 8; t++) {
                const int c = t * 8 + 2 * qid;
                ATS(pl0, c)     = tf32f(acc[t][0]);
                ATS(pl0, c + 1) = tf32f(acc[t][1]);
                ATS(pl1, c)     = tf32f(acc[t][2]);
                ATS(pl1, c + 1) = tf32f(acc[t][3]);
            }
        }
        __syncthreads();
        const int pg = p0 + half * 64;
        for (int i = tid; i < 1024; i += 256) {
            int pl = i >> 4, c4 = (i & 15) * 4;
            *(float4*)&g_p3h[((size_t)(b * cNP) + pg + pl) * 512 + h * 64 + c4] =
                *(float4*)&ATS(pl, c4);
        }
    }
#undef ATS
}

// =====================================================================
// fc_fused: Y1 = X @ W1 + b1 (no relu); out = relu([Y1, orig] @ W2 + b2).
// =====================================================================
__global__ __launch_bounds__(256) void fc_fused(const float* __restrict__ orig,
                                                const float* __restrict__ b1,
                                                const float* __restrict__ b2,
                                                float* __restrict__ out,
                                                int N, int which, int row_off) {
    const float* X = which ? g_p3h : g_l3h;
    const float* W1 = g_f1T[which];
    const float* W2 = g_f2T[which];
    __shared__ float As[64 * 68];
    __shared__ float Bs[64 * 68];
    const int row0 = blockIdx.x * 64;
    const int tid = threadIdx.x, wid = tid >> 5, lane = tid & 31, grp = lane >> 2, qid = lane & 3;
    const int mtw = wid & 3, nw = wid >> 2, m0 = mtw * 16, n0 = nw * 32;
    const int r0l = m0 + grp, r1l = r0l + 8;

    // ---- fc1 ----
    float acc[4][4] = {};
    for (int kt = 0; kt < 8; kt++) {
        const int kb = kt * 64;
        __syncthreads();
        for (int i = tid; i < 1024; i += 256) {
            int r = i >> 4, k4 = (i & 15) * 4;
            *(float4*)&AS(r, k4) = *(const float4*)&X[(size_t)(row0 + r) * 512 + kb + k4];
        }
        for (int i = tid; i < 1024; i += 256) {
            int n = i >> 4, k4 = (i & 15) * 4;
            *(float4*)&BS(n, k4) = *(const float4*)&W1[(size_t)n * 512 + kb + k4];
        }
        __syncthreads();
#pragma unroll
        for (int kk = 0; kk < 8; kk++) {
            uint32_t a[4];
            load_afr(As, m0, grp, qid, kk, a);
#pragma unroll
            for (int t = 0; t < 4; t++) {
                uint32_t bf[2];
                load_bfr(Bs, n0 + t * 8 + grp, kk, qid, bf);
                mma_tf32(acc[t], a, bf);
            }
        }
    }
    __syncthreads();
#pragma unroll
    for (int t = 0; t < 4; t++) {
        const int c = n0 + t * 8 + 2 * qid;
        const float bv0 = b1[c], bv1 = b1[c + 1];
        CS(r0l, c)     = tf32f(acc[t][0] + bv0);
        CS(r0l, c + 1) = tf32f(acc[t][1] + bv1);
        CS(r1l, c)     = tf32f(acc[t][2] + bv0);
        CS(r1l, c + 1) = tf32f(acc[t][3] + bv1);
    }
    for (int i = tid; i < 1024; i += 256) {
        int n = i >> 4, k4 = (i & 15) * 4;
        *(float4*)&BS(n, k4) = *(const float4*)&W2[(size_t)n * 128 + k4];
    }
    __syncthreads();

    // ---- fc2, kt0 (Y1) ----
    float acc2[4][4] = {};
#pragma unroll
    for (int kk = 0; kk < 8; kk++) {
        uint32_t a[4];
        load_afr(As, m0, grp, qid, kk, a);
#pragma unroll
        for (int t = 0; t < 4; t++) {
            uint32_t bf[2];
            load_bfr(Bs, n0 + t * 8 + grp, kk, qid, bf);
            mma_tf32(acc2[t], a, bf);
        }
    }
    __syncthreads();
    // ---- fc2, kt1 (orig) ----
    for (int i = tid; i < 1024; i += 256) {
        int r = i >> 4, c4 = (i & 15) * 4;
        float4 v = *(const float4*)&orig[(size_t)(row0 + r) * 64 + c4];
        v.x = tf32f(v.x); v.y = tf32f(v.y); v.z = tf32f(v.z); v.w = tf32f(v.w);
        *(float4*)&AS(r, c4) = v;
    }
    for (int i = tid; i < 1024; i += 256) {
        int n = i >> 4, k4 = (i & 15) * 4;
        *(float4*)&BS(n, k4) = *(const float4*)&W2[(size_t)n * 128 + 64 + k4];
    }
    __syncthreads();
#pragma unroll
    for (int kk = 0; kk < 8; kk++) {
        uint32_t a[4];
        load_afr(As, m0, grp, qid, kk, a);
#pragma unroll
        for (int t = 0; t < 4; t++) {
            uint32_t bf[2];
            load_bfr(Bs, n0 + t * 8 + grp, kk, qid, bf);
            mma_tf32(acc2[t], a, bf);
        }
    }
    __syncthreads();
#pragma unroll
    for (int t = 0; t < 4; t++) {
        const int c = n0 + t * 8 + 2 * qid;
        const float bv0 = b2[c], bv1 = b2[c + 1];
        CS(r0l, c)     = fmaxf(acc2[t][0] + bv0, 0.f);
        CS(r0l, c + 1) = fmaxf(acc2[t][1] + bv1, 0.f);
        CS(r1l, c)     = fmaxf(acc2[t][2] + bv0, 0.f);
        CS(r1l, c + 1) = fmaxf(acc2[t][3] + bv1, 0.f);
    }
    __syncthreads();
    const int b = row0 / N, nbase = row0 % N;
    for (int i = tid; i < 1024; i += 256) {
        int r = i >> 4, c4 = (i & 15) * 4;
        *(float4*)&out[((size_t)b * cNT + row_off + nbase + r) * 64 + c4] =
            *(float4*)&CS(r, c4);
    }
}

// =====================================================================
extern "C" void kernel_launch(void* const* d_in, const int* in_sizes, int n_in,
                              void* d_out, int out_size) {
    (void)in_sizes; (void)n_in; (void)out_size;
    const float* ligand = (const float*)d_in[0];
    const float* prot   = (const float*)d_in[1];
    const float* dist   = (const float*)d_in[2];
    const float* b_l1 = (const float*)d_in[4];
    const float* b_l2 = (const float*)d_in[6];
    const float* b_p1 = (const float*)d_in[8];
    const float* b_p2 = (const float*)d_in[10];
    const float* fc11_b = (const float*)d_in[12];
    const float* fc12_b = (const float*)d_in[14];
    const float* fc21_b = (const float*)d_in[16];
    const float* fc22_b = (const float*)d_in[18];
    float* out = (float*)d_out;

    prep_weights<<<832, 256>>>((const float*)d_in[3], (const float*)d_in[5],
                               (const float*)d_in[7], (const float*)d_in[9],
                               (const float*)d_in[11], (const float*)d_in[15],
                               (const float*)d_in[13], (const float*)d_in[17]);
    proj2<<<cB * cNL / 64, 256>>>(ligand, b_l1, b_l2, cNL, 0);
    proj2<<<cB * cNP / 64, 256>>>(prot, b_p1, b_p2, cNP, 1);
    energy_av<<<dim3(cNL / 32, cB * cH), 256>>>(dist);
    atv_mma<<<dim3(cNP / 128, cB * cH), 256>>>();
    fc_fused<<<cB * cNL / 64, 256>>>(ligand, fc11_b, fc12_b, out, cNL, 0, 0);
    fc_fused<<<cB * cNP / 64, 256>>>(prot, fc21_b, fc22_b, out, cNP, 1, cNL);
}

// round 9
// speedup vs baseline: 1.7358x; 1.3692x over previous
#include <cuda_runtime.h>
#include <math.h>
#include <stdint.h>

// Problem constants
constexpr int cB  = 16;
constexpr int cH  = 8;
constexpr int cNL = 256;
constexpr int cNP = 2048;
constexpr int cD  = 64;          // HID
constexpr int cNT = cNL + cNP;   // 2304

// ---------------- scratch (device globals; no runtime allocation) ----------------
__device__ float g_L1 [cB * cH * cNL * cD];         // [bh][l][d]   (tf32, relu)
__device__ float g_L2t[cB * cH * cD * cNL];         // [bh][d][l]
__device__ float g_P1 [cB * cH * cNP * cD];         // [bh][p][d]
__device__ float g_P2t[cB * cH * cD * cNP];         // [bh][d][p]
__device__ float g_att[(size_t)cB * cH * cNL * cNP];// e at historical max scale, tf32
__device__ float g_mthen[cB * cH * 32 * cNL];       // [bh][pt][l] running max at tile pt
__device__ float g_sinv[cB * cH * cNL];             // 1 / row-sum of e (final scale)
__device__ float g_l3h[cB * cNL * cH * cD];         // [B, Nl, 512] (tf32)
__device__ float g_p3h[cB * cNP * cH * cD];         // [B, Np, 512] (tf32)
// transposed + tf32-rounded weights
__device__ float g_wT [4][512 * 64];                // proj: [(h*64+n)][k]
__device__ float g_f1T[2][64 * 512];                // fc11/fc21: [n][k]
__device__ float g_f2T[2][64 * 128];                // fc12/fc22: [n][k]

// ---------------- tf32 helpers ----------------
__device__ __forceinline__ float tf32f(float x) {
    uint32_t u;
    asm("cvt.rna.tf32.f32 %0, %1;" : "=r"(u) : "f"(x));
    return __uint_as_float(u);
}

__device__ __forceinline__ void mma_tf32(float d[4], const uint32_t a[4], const uint32_t b[2]) {
    asm volatile(
        "mma.sync.aligned.m16n8k8.row.col.f32.tf32.tf32.f32 "
        "{%0,%1,%2,%3}, {%4,%5,%6,%7}, {%8,%9}, {%0,%1,%2,%3};\n"
        : "+f"(d[0]), "+f"(d[1]), "+f"(d[2]), "+f"(d[3])
        : "r"(a[0]), "r"(a[1]), "r"(a[2]), "r"(a[3]), "r"(b[0]), "r"(b[1]));
}

#define AS(r_, c_) As[(r_) * 68 + (c_)]
#define BS(r_, c_) Bs[(r_) * 68 + (c_)]
#define CS(r_, c_) As[(r_) * 68 + (c_)]   // stage aliases As region

__device__ __forceinline__ void load_afr(const float* As_, int m0, int grp, int qid,
                                         int kk, uint32_t a[4]) {
    const int k0 = kk * 8;
    a[0] = __float_as_uint(As_[(m0 + grp) * 68 + k0 + qid]);
    a[1] = __float_as_uint(As_[(m0 + grp + 8) * 68 + k0 + qid]);
    a[2] = __float_as_uint(As_[(m0 + grp) * 68 + k0 + qid + 4]);
    a[3] = __float_as_uint(As_[(m0 + grp + 8) * 68 + k0 + qid + 4]);
}

__device__ __forceinline__ void load_bfr(const float* Bs_, int n, int kk, int qid,
                                         uint32_t b[2]) {
    const int k0 = kk * 8;
    b[0] = __float_as_uint(Bs_[n * 68 + k0 + qid]);
    b[1] = __float_as_uint(Bs_[n * 68 + k0 + qid + 4]);
}

// =====================================================================
// prep: transpose + tf32-round all weights once.
// =====================================================================
__global__ __launch_bounds__(256) void prep_weights(
    const float* __restrict__ wl1, const float* __restrict__ wl2,
    const float* __restrict__ wp1, const float* __restrict__ wp2,
    const float* __restrict__ f11, const float* __restrict__ f21,
    const float* __restrict__ f12, const float* __restrict__ f22) {
    int i = blockIdx.x * 256 + threadIdx.x;
    if (i < 4 * 32768) {
        int w = i >> 15, r = i & 32767;          // r = hn*64 + k
        int hn = r >> 6, k = r & 63;
        const float* src = (w == 0) ? wl1 : (w == 1) ? wl2 : (w == 2) ? wp1 : wp2;
        g_wT[w][r] = tf32f(src[(size_t)k * 512 + hn]);
    } else if (i < 6 * 32768) {
        int j = i - 4 * 32768;
        int w = j >> 15, r = j & 32767;          // r = n*512 + k
        int n = r >> 9, k = r & 511;
        const float* src = w ? f21 : f11;
        g_f1T[w][r] = tf32f(src[(size_t)k * 64 + n]);
    } else if (i < 6 * 32768 + 2 * 8192) {
        int j = i - 6 * 32768;
        int w = j >> 13, r = j & 8191;           // r = n*128 + k
        int n = r >> 7, k = r & 127;
        const float* src = w ? f22 : f12;
        g_f2T[w][r] = tf32f(src[(size_t)k * 64 + n]);
    }
}

// =====================================================================
// proj2: both projections for one input. Block = 64 rows; x tile loaded once,
// A-fragments hoisted; loop over 16 (weight, head) B-tiles.
// =====================================================================
__global__ __launch_bounds__(256) void proj2(const float* __restrict__ x,
                                             const float* __restrict__ bA,
                                             const float* __restrict__ bB,
                                             int N, int which) {
    __shared__ float As[64 * 68];
    __shared__ float Bs[64 * 68];
    const int row0 = blockIdx.x * 64;
    const int tid = threadIdx.x;

    for (int i = tid; i < 1024; i += 256) {
        int r = i >> 4, c4 = (i & 15) * 4;
        float4 v = *(const float4*)&x[(size_t)(row0 + r) * 64 + c4];
        v.x = tf32f(v.x); v.y = tf32f(v.y); v.z = tf32f(v.z); v.w = tf32f(v.w);
        *(float4*)&AS(r, c4) = v;
    }
    __syncthreads();

    const int wid = tid >> 5, lane = tid & 31, grp = lane >> 2, qid = lane & 3;
    const int mtw = wid & 3, nw = wid >> 2;
    const int m0 = mtw * 16, n0 = nw * 32;
    uint32_t afr[8][4];
#pragma unroll
    for (int kk = 0; kk < 8; kk++) load_afr(As, m0, grp, qid, kk, afr[kk]);

    const int b = row0 / N, nbase = row0 % N;
    const int r0l = m0 + grp, r1l = r0l + 8;

    for (int it = 0; it < 16; it++) {
        const int wsel = it >> 3, h = it & 7;
        const float* wT = g_wT[which * 2 + wsel];
        const float* bias = wsel ? bB : bA;
        float* outp = (which == 0) ? (wsel ? g_L2t : g_L1) : (wsel ? g_P2t : g_P1);

        __syncthreads();   // prev iter's CS reads done
        for (int i = tid; i < 1024; i += 256) {
            int n = i >> 4, k4 = (i & 15) * 4;
            *(float4*)&BS(n, k4) = *(const float4*)&wT[(size_t)(h * 64 + n) * 64 + k4];
        }
        __syncthreads();

        float acc[4][4] = {};
#pragma unroll
        for (int kk = 0; kk < 8; kk++) {
#pragma unroll
            for (int t = 0; t < 4; t++) {
                uint32_t bf[2];
                load_bfr(Bs, n0 + t * 8 + grp, kk, qid, bf);
                mma_tf32(acc[t], afr[kk], bf);
            }
        }

        if (wsel == 0) {
#pragma unroll
            for (int t = 0; t < 4; t++) {
                int c = n0 + t * 8 + 2 * qid;
                float bv0 = bias[h * 64 + c], bv1 = bias[h * 64 + c + 1];
                CS(r0l, c)     = tf32f(fmaxf(acc[t][0] + bv0, 0.f));
                CS(r0l, c + 1) = tf32f(fmaxf(acc[t][1] + bv1, 0.f));
                CS(r1l, c)     = tf32f(fmaxf(acc[t][2] + bv0, 0.f));
                CS(r1l, c + 1) = tf32f(fmaxf(acc[t][3] + bv1, 0.f));
            }
            __syncthreads();
            for (int i = tid; i < 1024; i += 256) {
                int r = i >> 4, c4 = (i & 15) * 4;
                *(float4*)&outp[(((size_t)b * cH + h) * N + nbase + r) * 64 + c4] =
                    *(float4*)&CS(r, c4);
            }
        } else {
#pragma unroll
            for (int t = 0; t < 4; t++) {
                int c = n0 + t * 8 + 2 * qid;
                float bv0 = bias[h * 64 + c], bv1 = bias[h * 64 + c + 1];
                CS(c, r0l)     = tf32f(fmaxf(acc[t][0] + bv0, 0.f));
                CS(c + 1, r0l) = tf32f(fmaxf(acc[t][1] + bv1, 0.f));
                CS(c, r1l)     = tf32f(fmaxf(acc[t][2] + bv0, 0.f));
                CS(c + 1, r1l) = tf32f(fmaxf(acc[t][3] + bv1, 0.f));
            }
            __syncthreads();
            for (int i = tid; i < 1024; i += 256) {
                int d = i >> 4, r4 = (i & 15) * 4;
                *(float4*)&outp[(((size_t)b * cH + h) * 64 + d) * N + nbase + r4] =
                    *(float4*)&CS(d, r4);
            }
        }
    }
}

// =====================================================================
// energy_av: online softmax, warp-autonomous rows.
// Block = 128 threads (4 warps); each warp owns 16 full l-rows.
// e-stage OVERLAYS the P1 tile region (per-warp 16-row chunk, stride 68),
// guarded by barrier B3 (all warps done reading P1s). 3 block barriers/tile.
// =====================================================================
__global__ void __launch_bounds__(128, 4) energy_av(const float* __restrict__ dist) {
    __shared__ float P1s[64 * 68];       // L1 tile (init) / P1 tile / e-stage overlay
    __shared__ float P2s[64 * 68];       // P2 tiles
    const int bh = blockIdx.y, b = bh >> 3, h = bh & 7;
    const int l0 = blockIdx.x * 64;
    const int tid = threadIdx.x, wid = tid >> 5, lane = tid & 31;
    const int grp = lane >> 2, qid = lane & 3;

    // L1 tile -> P1s, hoist A fragments (warp wid owns rows wid*16..wid*16+15)
    const float* Ag = g_L1 + ((size_t)bh * cNL + l0) * 64;
    for (int i = tid; i < 1024; i += 128) {
        int r = i >> 4, c4 = (i & 15) * 4;
        *(float4*)&P1s[r * 68 + c4] = *(const float4*)&Ag[(size_t)r * 64 + c4];
    }
    __syncthreads();
    uint32_t afr[8][4];
#pragma unroll
    for (int kk = 0; kk < 8; kk++) load_afr(P1s, wid * 16, grp, qid, kk, afr[kk]);

    const float* Bbase = g_P1 + (size_t)bh * cNP * 64;
    const float* P2b   = g_P2t + (size_t)bh * 64 * cNP;
    float* ebase = g_att + ((size_t)bh * cNL + l0) * cNP;
    const int lr0 = wid * 16 + grp, lr1 = lr0 + 8;      // local row in 64-block
    const size_t drow0 = ((size_t)(b * cNL) + l0 + lr0) * cNP;
    const size_t drow1 = ((size_t)(b * cNL) + l0 + lr1) * cNP;
    float* estw = &P1s[wid * 16 * 68];   // e-stage: warp-private 16x68 chunk
    const float hf = (float)h;

    float mold0 = 0.f, mold1 = 0.f, s0 = 0.f, s1 = 0.f;  // masked logits = 0
    float accv[8][4] = {};   // av accumulator over d (8 n-tiles)

    for (int pt = 0; pt < 32; pt++) {
        const int p0 = pt * 64;
        __syncthreads();                     // B1: prev tile fully consumed
        for (int i = tid; i < 1024; i += 128) {
            int p = i >> 4, k4 = (i & 15) * 4;
            *(float4*)&P1s[p * 68 + k4] = *(const float4*)&Bbase[(size_t)(p0 + p) * 64 + k4];
        }
        for (int i = tid; i < 1024; i += 128) {
            int dd = i >> 4, p4 = (i & 15) * 4;
            *(float4*)&P2s[dd * 68 + p4] = *(const float4*)&P2b[(size_t)dd * cNP + p0 + p4];
        }
        __syncthreads();                     // B2: tiles ready

        // energy MMA: m=16 (own rows) x n=64 (full tile)
        float acc[8][4] = {};
#pragma unroll
        for (int kk = 0; kk < 8; kk++)
#pragma unroll
            for (int t = 0; t < 8; t++) {
                uint32_t bf[2];
                load_bfr(P1s, t * 8 + grp, kk, qid, bf);
                mma_tf32(acc[t], afr[kk], bf);
            }

        // mask + logits (in place) + tile max
        float tx0 = -1e30f, tx1 = -1e30f;
#pragma unroll
        for (int t = 0; t < 8; t++) {
            const int c = p0 + t * 8 + 2 * qid;
            const float2 dv0 = *(const float2*)&dist[drow0 + c];
            const float2 dv1 = *(const float2*)&dist[drow1 + c];
            const float dd[4] = {dv0.x, dv0.y, dv1.x, dv1.y};
#pragma unroll
            for (int j = 0; j < 4; j++) {
                const float d = dd[j];
                const bool msk = (h < 7) ? (d > hf && d <= hf + 3.0f) : (d > 7.0f);
                const float inter = msk ? __fdividef(1.0f, d) : 0.0f;
                acc[t][j] = acc[t][j] * 0.125f * inter;
            }
            tx0 = fmaxf(tx0, fmaxf(acc[t][0], acc[t][1]));
            tx1 = fmaxf(tx1, fmaxf(acc[t][2], acc[t][3]));
        }
        tx0 = fmaxf(tx0, __shfl_xor_sync(0xffffffffu, tx0, 1));
        tx0 = fmaxf(tx0, __shfl_xor_sync(0xffffffffu, tx0, 2));
        tx1 = fmaxf(tx1, __shfl_xor_sync(0xffffffffu, tx1, 1));
        tx1 = fmaxf(tx1, __shfl_xor_sync(0xffffffffu, tx1, 2));
        const float mn0 = fmaxf(mold0, tx0), mn1 = fmaxf(mold1, tx1);
        const float f0 = __expf(mold0 - mn0), f1 = __expf(mold1 - mn1);
        mold0 = mn0; mold1 = mn1;

        __syncthreads();                     // B3: all warps done reading P1s

        float ps0 = 0.f, ps1 = 0.f;
#pragma unroll
        for (int t = 0; t < 8; t++) {
            float e0 = tf32f(__expf(acc[t][0] - mn0));
            float e1 = tf32f(__expf(acc[t][1] - mn0));
            float e2 = tf32f(__expf(acc[t][2] - mn1));
            float e3 = tf32f(__expf(acc[t][3] - mn1));
            ps0 += e0 + e1; ps1 += e2 + e3;
            const int cc = t * 8 + 2 * qid;
            *(float2*)&estw[grp * 68 + cc]       = make_float2(e0, e1);
            *(float2*)&estw[(grp + 8) * 68 + cc] = make_float2(e2, e3);
            *(float2*)&ebase[(size_t)lr0 * cNP + p0 + cc] = make_float2(e0, e1);
            *(float2*)&ebase[(size_t)lr1 * cNP + p0 + cc] = make_float2(e2, e3);
            // rescale av accumulator
            accv[t][0] *= f0; accv[t][1] *= f0; accv[t][2] *= f1; accv[t][3] *= f1;
        }
        s0 = s0 * f0 + ps0; s1 = s1 * f1 + ps1;
        if (qid == 0) {
            g_mthen[((size_t)bh * 32 + pt) * cNL + l0 + lr0] = mn0;
            g_mthen[((size_t)bh * 32 + pt) * cNL + l0 + lr1] = mn1;
        }
        __syncwarp();                        // est visible within warp

        // av MMA: A = e (est, K=p tile), B = P2 tile; accumulate over d tiles
#pragma unroll
        for (int kk = 0; kk < 8; kk++) {
            const int k0 = kk * 8;
            uint32_t a[4] = { __float_as_uint(estw[grp * 68 + k0 + qid]),
                              __float_as_uint(estw[(grp + 8) * 68 + k0 + qid]),
                              __float_as_uint(estw[grp * 68 + k0 + qid + 4]),
                              __float_as_uint(estw[(grp + 8) * 68 + k0 + qid + 4]) };
#pragma unroll
            for (int t = 0; t < 8; t++) {
                uint32_t bf[2];
                load_bfr(P2s, t * 8 + grp, kk, qid, bf);
                mma_tf32(accv[t], a, bf);
            }
        }
    }

    // finalize: quad-reduce sums, write sinv + l3h
    s0 += __shfl_xor_sync(0xffffffffu, s0, 1);
    s0 += __shfl_xor_sync(0xffffffffu, s0, 2);
    s1 += __shfl_xor_sync(0xffffffffu, s1, 1);
    s1 += __shfl_xor_sync(0xffffffffu, s1, 2);
    const float inv0 = 1.0f / s0, inv1 = 1.0f / s1;
    if (qid == 0) {
        g_sinv[bh * cNL + l0 + lr0] = inv0;
        g_sinv[bh * cNL + l0 + lr1] = inv1;
    }
    const size_t orow0 = ((size_t)(b * cNL) + l0 + lr0) * 512 + h * 64;
    const size_t orow1 = ((size_t)(b * cNL) + l0 + lr1) * 512 + h * 64;
#pragma unroll
    for (int t = 0; t < 8; t++) {
        const int cc = t * 8 + 2 * qid;
        *(float2*)&g_l3h[orow0 + cc] =
            make_float2(tf32f(accv[t][0] * inv0), tf32f(accv[t][1] * inv0));
        *(float2*)&g_l3h[orow1 + cc] =
            make_float2(tf32f(accv[t][2] * inv1), tf32f(accv[t][3] * inv1));
    }
}

// =====================================================================
// atv: p3h[b,p,h*64+d] = sum_l e[l,p]*cf[l,pt] * (L2t[d,l] * sinv[l]).
// cf[l,pt] = exp(m_then[pt][l] - m_final[l]) corrects historical e scale.
// =====================================================================
__global__ __launch_bounds__(256) void atv_mma() {
    __shared__ float Ae[128 * 36];   // e^T [p][l]
    __shared__ float Bl[64 * 36];    // scaled L2t [d][l]
    __shared__ float cfa[2][256];    // corrections for this block's 2 p-tiles
#define ATS(p_, c_) Ae[(p_) * 68 + (c_)]   // epilogue stage overlays Ae
    const int bh = blockIdx.y, b = bh >> 3, h = bh & 7;
    const int p0 = blockIdx.x * 128;
    const int tid = threadIdx.x, wid = tid >> 5, lane = tid & 31, grp = lane >> 2, qid = lane & 3;
    const int m0 = wid * 16;
    const float* eb = g_att + (size_t)bh * cNL * cNP;
    const float* L2b = g_L2t + (size_t)bh * 64 * cNL;
    const float* sv = g_sinv + (size_t)bh * cNL;
    const int pt0 = p0 >> 6;

    for (int i = tid; i < 512; i += 256) {
        int v = i >> 8, j = i & 255;
        float mf = g_mthen[((size_t)bh * 32 + 31) * cNL + j];
        float mt = g_mthen[((size_t)bh * 32 + pt0 + v) * cNL + j];
        cfa[v][j] = __expf(mt - mf);
    }

    float acc[8][4] = {};
    for (int lt = 0; lt < 8; lt++) {
        const int lb = lt * 32;
        __syncthreads();   // also guards cfa readiness on first iter
        for (int i = tid; i < 4096; i += 256) {
            int r = i >> 7, c = i & 127;    // r = l local, c = p local
            Ae[c * 36 + r] = tf32f(eb[(size_t)(lb + r) * cNP + p0 + c] * cfa[c >> 6][lb + r]);
        }
        for (int i = tid; i < 2048; i += 256) {
            int d = i >> 5, k = i & 31;
            Bl[d * 36 + k] = tf32f(L2b[(size_t)d * cNL + lb + k] * sv[lb + k]);
        }
        __syncthreads();
#pragma unroll
        for (int kk = 0; kk < 4; kk++) {
            const int k0 = kk * 8;
            uint32_t a[4] = { __float_as_uint(Ae[(m0 + grp) * 36 + k0 + qid]),
                              __float_as_uint(Ae[(m0 + grp + 8) * 36 + k0 + qid]),
                              __float_as_uint(Ae[(m0 + grp) * 36 + k0 + qid + 4]),
                              __float_as_uint(Ae[(m0 + grp + 8) * 36 + k0 + qid + 4]) };
#pragma unroll
            for (int t = 0; t < 8; t++) {
                uint32_t bf[2] = { __float_as_uint(Bl[(t * 8 + grp) * 36 + k0 + qid]),
                                   __float_as_uint(Bl[(t * 8 + grp) * 36 + k0 + qid + 4]) };
                mma_tf32(acc[t], a, bf);
            }
        }
    }

#pragma unroll
    for (int half = 0; half < 2; half++) {
        __syncthreads();
        if ((wid >> 2) == half) {
            const int pl0 = (m0 & 63) + grp, pl1 = pl0 + 8;
#pragma unroll
            for (int t = 0; t < 8; t++) {
                const int c = t * 8 + 2 * qid;
                ATS(pl0, c)     = tf32f(acc[t][0]);
                ATS(pl0, c + 1) = tf32f(acc[t][1]);
                ATS(pl1, c)     = tf32f(acc[t][2]);
                ATS(pl1, c + 1) = tf32f(acc[t][3]);
            }
        }
        __syncthreads();
        const int pg = p0 + half * 64;
        for (int i = tid; i < 1024; i += 256) {
            int pl = i >> 4, c4 = (i & 15) * 4;
            *(float4*)&g_p3h[((size_t)(b * cNP) + pg + pl) * 512 + h * 64 + c4] =
                *(float4*)&ATS(pl, c4);
        }
    }
#undef ATS
}

// =====================================================================
// fc_fused: Y1 = X @ W1 + b1 (no relu); out = relu([Y1, orig] @ W2 + b2).
// =====================================================================
__global__ __launch_bounds__(256) void fc_fused(const float* __restrict__ orig,
                                                const float* __restrict__ b1,
                                                const float* __restrict__ b2,
                                                float* __restrict__ out,
                                                int N, int which, int row_off) {
    const float* X = which ? g_p3h : g_l3h;
    const float* W1 = g_f1T[which];
    const float* W2 = g_f2T[which];
    __shared__ float As[64 * 68];
    __shared__ float Bs[64 * 68];
    const int row0 = blockIdx.x * 64;
    const int tid = threadIdx.x, wid = tid >> 5, lane = tid & 31, grp = lane >> 2, qid = lane & 3;
    const int mtw = wid & 3, nw = wid >> 2, m0 = mtw * 16, n0 = nw * 32;
    const int r0l = m0 + grp, r1l = r0l + 8;

    // ---- fc1 ----
    float acc[4][4] = {};
    for (int kt = 0; kt < 8; kt++) {
        const int kb = kt * 64;
        __syncthreads();
        for (int i = tid; i < 1024; i += 256) {
            int r = i >> 4, k4 = (i & 15) * 4;
            *(float4*)&AS(r, k4) = *(const float4*)&X[(size_t)(row0 + r) * 512 + kb + k4];
        }
        for (int i = tid; i < 1024; i += 256) {
            int n = i >> 4, k4 = (i & 15) * 4;
            *(float4*)&BS(n, k4) = *(const float4*)&W1[(size_t)n * 512 + kb + k4];
        }
        __syncthreads();
#pragma unroll
        for (int kk = 0; kk < 8; kk++) {
            uint32_t a[4];
            load_afr(As, m0, grp, qid, kk, a);
#pragma unroll
            for (int t = 0; t < 4; t++) {
                uint32_t bf[2];
                load_bfr(Bs, n0 + t * 8 + grp, kk, qid, bf);
                mma_tf32(acc[t], a, bf);
            }
        }
    }
    __syncthreads();
#pragma unroll
    for (int t = 0; t < 4; t++) {
        const int c = n0 + t * 8 + 2 * qid;
        const float bv0 = b1[c], bv1 = b1[c + 1];
        CS(r0l, c)     = tf32f(acc[t][0] + bv0);
        CS(r0l, c + 1) = tf32f(acc[t][1] + bv1);
        CS(r1l, c)     = tf32f(acc[t][2] + bv0);
        CS(r1l, c + 1) = tf32f(acc[t][3] + bv1);
    }
    for (int i = tid; i < 1024; i += 256) {
        int n = i >> 4, k4 = (i & 15) * 4;
        *(float4*)&BS(n, k4) = *(const float4*)&W2[(size_t)n * 128 + k4];
    }
    __syncthreads();

    // ---- fc2, kt0 (Y1) ----
    float acc2[4][4] = {};
#pragma unroll
    for (int kk = 0; kk < 8; kk++) {
        uint32_t a[4];
        load_afr(As, m0, grp, qid, kk, a);
#pragma unroll
        for (int t = 0; t < 4; t++) {
            uint32_t bf[2];
            load_bfr(Bs, n0 + t * 8 + grp, kk, qid, bf);
            mma_tf32(acc2[t], a, bf);
        }
    }
    __syncthreads();
    // ---- fc2, kt1 (orig) ----
    for (int i = tid; i < 1024; i += 256) {
        int r = i >> 4, c4 = (i & 15) * 4;
        float4 v = *(const float4*)&orig[(size_t)(row0 + r) * 64 + c4];
        v.x = tf32f(v.x); v.y = tf32f(v.y); v.z = tf32f(v.z); v.w = tf32f(v.w);
        *(float4*)&AS(r, c4) = v;
    }
    for (int i = tid; i < 1024; i += 256) {
        int n = i >> 4, k4 = (i & 15) * 4;
        *(float4*)&BS(n, k4) = *(const float4*)&W2[(size_t)n * 128 + 64 + k4];
    }
    __syncthreads();
#pragma unroll
    for (int kk = 0; kk < 8; kk++) {
        uint32_t a[4];
        load_afr(As, m0, grp, qid, kk, a);
#pragma unroll
        for (int t = 0; t < 4; t++) {
            uint32_t bf[2];
            load_bfr(Bs, n0 + t * 8 + grp, kk, qid, bf);
            mma_tf32(acc2[t], a, bf);
        }
    }
    __syncthreads();
#pragma unroll
    for (int t = 0; t < 4; t++) {
        const int c = n0 + t * 8 + 2 * qid;
        const float bv0 = b2[c], bv1 = b2[c + 1];
        CS(r0l, c)     = fmaxf(acc2[t][0] + bv0, 0.f);
        CS(r0l, c + 1) = fmaxf(acc2[t][1] + bv1, 0.f);
        CS(r1l, c)     = fmaxf(acc2[t][2] + bv0, 0.f);
        CS(r1l, c + 1) = fmaxf(acc2[t][3] + bv1, 0.f);
    }
    __syncthreads();
    const int b = row0 / N, nbase = row0 % N;
    for (int i = tid; i < 1024; i += 256) {
        int r = i >> 4, c4 = (i & 15) * 4;
        *(float4*)&out[((size_t)b * cNT + row_off + nbase + r) * 64 + c4] =
            *(float4*)&CS(r, c4);
    }
}

// =====================================================================
extern "C" void kernel_launch(void* const* d_in, const int* in_sizes, int n_in,
                              void* d_out, int out_size) {
    (void)in_sizes; (void)n_in; (void)out_size;
    const float* ligand = (const float*)d_in[0];
    const float* prot   = (const float*)d_in[1];
    const float* dist   = (const float*)d_in[2];
    const float* b_l1 = (const float*)d_in[4];
    const float* b_l2 = (const float*)d_in[6];
    const float* b_p1 = (const float*)d_in[8];
    const float* b_p2 = (const float*)d_in[10];
    const float* fc11_b = (const float*)d_in[12];
    const float* fc12_b = (const float*)d_in[14];
    const float* fc21_b = (const float*)d_in[16];
    const float* fc22_b = (const float*)d_in[18];
    float* out = (float*)d_out;

    prep_weights<<<832, 256>>>((const float*)d_in[3], (const float*)d_in[5],
                               (const float*)d_in[7], (const float*)d_in[9],
                               (const float*)d_in[11], (const float*)d_in[15],
                               (const float*)d_in[13], (const float*)d_in[17]);
    proj2<<<cB * cNL / 64, 256>>>(ligand, b_l1, b_l2, cNL, 0);
    proj2<<<cB * cNP / 64, 256>>>(prot, b_p1, b_p2, cNP, 1);
    energy_av<<<dim3(cNL / 64, cB * cH), 128>>>(dist);
    atv_mma<<<dim3(cNP / 128, cB * cH), 256>>>();
    fc_fused<<<cB * cNL / 64, 256>>>(ligand, fc11_b, fc12_b, out, cNL, 0, 0);
    fc_fused<<<cB * cNP / 64, 256>>>(prot, fc21_b, fc22_b, out, cNP, 1, cNL);
}

// round 10
// speedup vs baseline: 2.2599x; 1.3019x over previous
#include <cuda_runtime.h>
#include <math.h>
#include <stdint.h>

// Problem constants
constexpr int cB  = 16;
constexpr int cH  = 8;
constexpr int cNL = 256;
constexpr int cNP = 2048;
constexpr int cD  = 64;          // HID
constexpr int cNT = cNL + cNP;   // 2304

// ---------------- scratch (device globals; no runtime allocation) ----------------
__device__ float g_L1 [cB * cH * cNL * cD];         // [bh][l][d]   (tf32, relu)
__device__ float g_L2t[cB * cH * cD * cNL];         // [bh][d][l]
__device__ float g_P1 [cB * cH * cNP * cD];         // [bh][p][d]
__device__ float g_P2t[cB * cH * cD * cNP];         // [bh][d][p]
__device__ float g_att[(size_t)cB * cH * cNL * cNP];// e at historical max scale, tf32
__device__ float g_mthen[cB * cH * 32 * cNL];       // [bh][pt][l] running max at tile pt
__device__ float g_sinv[cB * cH * cNL];             // 1 / row-sum of e (final scale)
__device__ float g_l3h[cB * cNL * cH * cD];         // [B, Nl, 512] (tf32)
__device__ float g_p3h[cB * cNP * cH * cD];         // [B, Np, 512] (tf32)
// transposed + tf32-rounded weights
__device__ float g_wT [4][512 * 64];                // proj: [(h*64+n)][k]
__device__ float g_f1T[2][64 * 512];                // fc11/fc21: [n][k]
__device__ float g_f2T[2][64 * 128];                // fc12/fc22: [n][k]

// ---------------- tf32 / cp.async helpers ----------------
__device__ __forceinline__ float tf32f(float x) {
    uint32_t u;
    asm("cvt.rna.tf32.f32 %0, %1;" : "=r"(u) : "f"(x));
    return __uint_as_float(u);
}

__device__ __forceinline__ void mma_tf32(float d[4], const uint32_t a[4], const uint32_t b[2]) {
    asm volatile(
        "mma.sync.aligned.m16n8k8.row.col.f32.tf32.tf32.f32 "
        "{%0,%1,%2,%3}, {%4,%5,%6,%7}, {%8,%9}, {%0,%1,%2,%3};\n"
        : "+f"(d[0]), "+f"(d[1]), "+f"(d[2]), "+f"(d[3])
        : "r"(a[0]), "r"(a[1]), "r"(a[2]), "r"(a[3]), "r"(b[0]), "r"(b[1]));
}

__device__ __forceinline__ void cpa16(float* smem, const float* g) {
    uint32_t s = (uint32_t)__cvta_generic_to_shared(smem);
    asm volatile("cp.async.cg.shared.global [%0], [%1], 16;" :: "r"(s), "l"(g) : "memory");
}
#define CP_COMMIT() asm volatile("cp.async.commit_group;" ::: "memory")
#define CP_WAIT(n)  asm volatile("cp.async.wait_group %0;" :: "n"(n) : "memory")

#define AS(r_, c_) As[(r_) * 68 + (c_)]
#define BS(r_, c_) Bs[(r_) * 68 + (c_)]
#define CS(r_, c_) As[(r_) * 68 + (c_)]   // stage aliases As region

__device__ __forceinline__ void load_afr(const float* As_, int m0, int grp, int qid,
                                         int kk, uint32_t a[4]) {
    const int k0 = kk * 8;
    a[0] = __float_as_uint(As_[(m0 + grp) * 68 + k0 + qid]);
    a[1] = __float_as_uint(As_[(m0 + grp + 8) * 68 + k0 + qid]);
    a[2] = __float_as_uint(As_[(m0 + grp) * 68 + k0 + qid + 4]);
    a[3] = __float_as_uint(As_[(m0 + grp + 8) * 68 + k0 + qid + 4]);
}

__device__ __forceinline__ void load_bfr(const float* Bs_, int n, int kk, int qid,
                                         uint32_t b[2]) {
    const int k0 = kk * 8;
    b[0] = __float_as_uint(Bs_[n * 68 + k0 + qid]);
    b[1] = __float_as_uint(Bs_[n * 68 + k0 + qid + 4]);
}

// =====================================================================
// prep: transpose + tf32-round all weights once.
// =====================================================================
__global__ __launch_bounds__(256) void prep_weights(
    const float* __restrict__ wl1, const float* __restrict__ wl2,
    const float* __restrict__ wp1, const float* __restrict__ wp2,
    const float* __restrict__ f11, const float* __restrict__ f21,
    const float* __restrict__ f12, const float* __restrict__ f22) {
    int i = blockIdx.x * 256 + threadIdx.x;
    if (i < 4 * 32768) {
        int w = i >> 15, r = i & 32767;          // r = hn*64 + k
        int hn = r >> 6, k = r & 63;
        const float* src = (w == 0) ? wl1 : (w == 1) ? wl2 : (w == 2) ? wp1 : wp2;
        g_wT[w][r] = tf32f(src[(size_t)k * 512 + hn]);
    } else if (i < 6 * 32768) {
        int j = i - 4 * 32768;
        int w = j >> 15, r = j & 32767;          // r = n*512 + k
        int n = r >> 9, k = r & 511;
        const float* src = w ? f21 : f11;
        g_f1T[w][r] = tf32f(src[(size_t)k * 64 + n]);
    } else if (i < 6 * 32768 + 2 * 8192) {
        int j = i - 6 * 32768;
        int w = j >> 13, r = j & 8191;           // r = n*128 + k
        int n = r >> 7, k = r & 127;
        const float* src = w ? f22 : f12;
        g_f2T[w][r] = tf32f(src[(size_t)k * 64 + n]);
    }
}

// =====================================================================
// proj2 (merged lig+prot): both projections per input. Block = 64 rows;
// x tile loaded once, A-fragments hoisted; 16 (weight, head) B-tiles via cp.async.
// blocks 0..63 -> ligand (N=256); 64..575 -> prot (N=2048).
// =====================================================================
__global__ __launch_bounds__(256) void proj2(const float* __restrict__ lig,
                                             const float* __restrict__ prot,
                                             const float* __restrict__ bl1,
                                             const float* __restrict__ bl2,
                                             const float* __restrict__ bp1,
                                             const float* __restrict__ bp2) {
    __shared__ float As[64 * 68];
    __shared__ float Bs[64 * 68];
    const int which = (blockIdx.x >= 64) ? 1 : 0;
    const int bx = which ? (blockIdx.x - 64) : blockIdx.x;
    const float* x = which ? prot : lig;
    const float* bA = which ? bp1 : bl1;
    const float* bB = which ? bp2 : bl2;
    const int N = which ? cNP : cNL;
    const int row0 = bx * 64;
    const int tid = threadIdx.x;

    for (int i = tid; i < 1024; i += 256) {
        int r = i >> 4, c4 = (i & 15) * 4;
        float4 v = *(const float4*)&x[(size_t)(row0 + r) * 64 + c4];
        v.x = tf32f(v.x); v.y = tf32f(v.y); v.z = tf32f(v.z); v.w = tf32f(v.w);
        *(float4*)&AS(r, c4) = v;
    }
    __syncthreads();

    const int wid = tid >> 5, lane = tid & 31, grp = lane >> 2, qid = lane & 3;
    const int mtw = wid & 3, nw = wid >> 2;
    const int m0 = mtw * 16, n0 = nw * 32;
    uint32_t afr[8][4];
#pragma unroll
    for (int kk = 0; kk < 8; kk++) load_afr(As, m0, grp, qid, kk, afr[kk]);

    const int b = row0 / N, nbase = row0 % N;
    const int r0l = m0 + grp, r1l = r0l + 8;

    for (int it = 0; it < 16; it++) {
        const int wsel = it >> 3, h = it & 7;
        const float* wT = g_wT[which * 2 + wsel];
        const float* bias = wsel ? bB : bA;
        float* outp = (which == 0) ? (wsel ? g_L2t : g_L1) : (wsel ? g_P2t : g_P1);

        __syncthreads();   // prev iter's CS reads done
        for (int i = tid; i < 1024; i += 256) {
            int n = i >> 4, k4 = (i & 15) * 4;
            cpa16(&BS(n, k4), &wT[(size_t)(h * 64 + n) * 64 + k4]);
        }
        CP_COMMIT();
        CP_WAIT(0);
        __syncthreads();

        float acc[4][4] = {};
#pragma unroll
        for (int kk = 0; kk < 8; kk++) {
#pragma unroll
            for (int t = 0; t < 4; t++) {
                uint32_t bf[2];
                load_bfr(Bs, n0 + t * 8 + grp, kk, qid, bf);
                mma_tf32(acc[t], afr[kk], bf);
            }
        }

        if (wsel == 0) {
#pragma unroll
            for (int t = 0; t < 4; t++) {
                int c = n0 + t * 8 + 2 * qid;
                float bv0 = bias[h * 64 + c], bv1 = bias[h * 64 + c + 1];
                CS(r0l, c)     = tf32f(fmaxf(acc[t][0] + bv0, 0.f));
                CS(r0l, c + 1) = tf32f(fmaxf(acc[t][1] + bv1, 0.f));
                CS(r1l, c)     = tf32f(fmaxf(acc[t][2] + bv0, 0.f));
                CS(r1l, c + 1) = tf32f(fmaxf(acc[t][3] + bv1, 0.f));
            }
            __syncthreads();
            for (int i = tid; i < 1024; i += 256) {
                int r = i >> 4, c4 = (i & 15) * 4;
                *(float4*)&outp[(((size_t)b * cH + h) * N + nbase + r) * 64 + c4] =
                    *(float4*)&CS(r, c4);
            }
        } else {
#pragma unroll
            for (int t = 0; t < 4; t++) {
                int c = n0 + t * 8 + 2 * qid;
                float bv0 = bias[h * 64 + c], bv1 = bias[h * 64 + c + 1];
                CS(c, r0l)     = tf32f(fmaxf(acc[t][0] + bv0, 0.f));
                CS(c + 1, r0l) = tf32f(fmaxf(acc[t][1] + bv1, 0.f));
                CS(c, r1l)     = tf32f(fmaxf(acc[t][2] + bv0, 0.f));
                CS(c + 1, r1l) = tf32f(fmaxf(acc[t][3] + bv1, 0.f));
            }
            __syncthreads();
            for (int i = tid; i < 1024; i += 256) {
                int d = i >> 4, r4 = (i & 15) * 4;
                *(float4*)&outp[(((size_t)b * cH + h) * 64 + d) * N + nbase + r4] =
                    *(float4*)&CS(d, r4);
            }
        }
    }
}

// =====================================================================
// energy_av: online softmax, warp-autonomous rows, cp.async tile fills.
// P1 and P2 committed as separate groups: P2 load overlaps energy MMA.
// Block = 128 threads (4 warps); each warp owns 16 full l-rows.
// =====================================================================
__global__ void __launch_bounds__(128, 4) energy_av(const float* __restrict__ dist) {
    __shared__ float P1s[64 * 68];       // L1 tile (init) / P1 tile / e-stage overlay
    __shared__ float P2s[64 * 68];       // P2 tiles
    const int bh = blockIdx.y, b = bh >> 3, h = bh & 7;
    const int l0 = blockIdx.x * 64;
    const int tid = threadIdx.x, wid = tid >> 5, lane = tid & 31;
    const int grp = lane >> 2, qid = lane & 3;

    // L1 tile -> P1s (cp.async), hoist A fragments
    const float* Ag = g_L1 + ((size_t)bh * cNL + l0) * 64;
    for (int i = tid; i < 1024; i += 128) {
        int r = i >> 4, c4 = (i & 15) * 4;
        cpa16(&P1s[r * 68 + c4], &Ag[(size_t)r * 64 + c4]);
    }
    CP_COMMIT();
    CP_WAIT(0);
    __syncthreads();
    uint32_t afr[8][4];
#pragma unroll
    for (int kk = 0; kk < 8; kk++) load_afr(P1s, wid * 16, grp, qid, kk, afr[kk]);

    const float* Bbase = g_P1 + (size_t)bh * cNP * 64;
    const float* P2b   = g_P2t + (size_t)bh * 64 * cNP;
    float* ebase = g_att + ((size_t)bh * cNL + l0) * cNP;
    const int lr0 = wid * 16 + grp, lr1 = lr0 + 8;      // local row in 64-block
    const size_t drow0 = ((size_t)(b * cNL) + l0 + lr0) * cNP;
    const size_t drow1 = ((size_t)(b * cNL) + l0 + lr1) * cNP;
    float* estw = &P1s[wid * 16 * 68];   // e-stage: warp-private 16x68 chunk
    const float hf = (float)h;

    float mold0 = 0.f, mold1 = 0.f, s0 = 0.f, s1 = 0.f;  // masked logits = 0
    float accv[8][4] = {};   // av accumulator over d (8 n-tiles)

    for (int pt = 0; pt < 32; pt++) {
        const int p0 = pt * 64;
        __syncthreads();                     // B1: prev tile fully consumed
        for (int i = tid; i < 1024; i += 128) {
            int p = i >> 4, k4 = (i & 15) * 4;
            cpa16(&P1s[p * 68 + k4], &Bbase[(size_t)(p0 + p) * 64 + k4]);
        }
        CP_COMMIT();                         // group A: P1 tile
        for (int i = tid; i < 1024; i += 128) {
            int dd = i >> 4, p4 = (i & 15) * 4;
            cpa16(&P2s[dd * 68 + p4], &P2b[(size_t)dd * cNP + p0 + p4]);
        }
        CP_COMMIT();                         // group B: P2 tile
        CP_WAIT(1);                          // P1 landed; P2 still in flight
        __syncthreads();                     // B2: P1 visible block-wide

        // energy MMA: m=16 (own rows) x n=64 (full tile)
        float acc[8][4] = {};
#pragma unroll
        for (int kk = 0; kk < 8; kk++)
#pragma unroll
            for (int t = 0; t < 8; t++) {
                uint32_t bf[2];
                load_bfr(P1s, t * 8 + grp, kk, qid, bf);
                mma_tf32(acc[t], afr[kk], bf);
            }

        // mask + logits (in place) + tile max
        float tx0 = -1e30f, tx1 = -1e30f;
#pragma unroll
        for (int t = 0; t < 8; t++) {
            const int c = p0 + t * 8 + 2 * qid;
            const float2 dv0 = *(const float2*)&dist[drow0 + c];
            const float2 dv1 = *(const float2*)&dist[drow1 + c];
            const float dd[4] = {dv0.x, dv0.y, dv1.x, dv1.y};
#pragma unroll
            for (int j = 0; j < 4; j++) {
                const float d = dd[j];
                const bool msk = (h < 7) ? (d > hf && d <= hf + 3.0f) : (d > 7.0f);
                const float inter = msk ? __fdividef(1.0f, d) : 0.0f;
                acc[t][j] = acc[t][j] * 0.125f * inter;
            }
            tx0 = fmaxf(tx0, fmaxf(acc[t][0], acc[t][1]));
            tx1 = fmaxf(tx1, fmaxf(acc[t][2], acc[t][3]));
        }
        tx0 = fmaxf(tx0, __shfl_xor_sync(0xffffffffu, tx0, 1));
        tx0 = fmaxf(tx0, __shfl_xor_sync(0xffffffffu, tx0, 2));
        tx1 = fmaxf(tx1, __shfl_xor_sync(0xffffffffu, tx1, 1));
        tx1 = fmaxf(tx1, __shfl_xor_sync(0xffffffffu, tx1, 2));
        const float mn0 = fmaxf(mold0, tx0), mn1 = fmaxf(mold1, tx1);
        const float f0 = __expf(mold0 - mn0), f1 = __expf(mold1 - mn1);
        mold0 = mn0; mold1 = mn1;

        CP_WAIT(0);                          // P2 landed (overlapped with MMA)
        __syncthreads();                     // B3: P1s reads done + P2 visible

        float ps0 = 0.f, ps1 = 0.f;
#pragma unroll
        for (int t = 0; t < 8; t++) {
            float e0 = tf32f(__expf(acc[t][0] - mn0));
            float e1 = tf32f(__expf(acc[t][1] - mn0));
            float e2 = tf32f(__expf(acc[t][2] - mn1));
            float e3 = tf32f(__expf(acc[t][3] - mn1));
            ps0 += e0 + e1; ps1 += e2 + e3;
            const int cc = t * 8 + 2 * qid;
            *(float2*)&estw[grp * 68 + cc]       = make_float2(e0, e1);
            *(float2*)&estw[(grp + 8) * 68 + cc] = make_float2(e2, e3);
            *(float2*)&ebase[(size_t)lr0 * cNP + p0 + cc] = make_float2(e0, e1);
            *(float2*)&ebase[(size_t)lr1 * cNP + p0 + cc] = make_float2(e2, e3);
            // rescale av accumulator
            accv[t][0] *= f0; accv[t][1] *= f0; accv[t][2] *= f1; accv[t][3] *= f1;
        }
        s0 = s0 * f0 + ps0; s1 = s1 * f1 + ps1;
        if (qid == 0) {
            g_mthen[((size_t)bh * 32 + pt) * cNL + l0 + lr0] = mn0;
            g_mthen[((size_t)bh * 32 + pt) * cNL + l0 + lr1] = mn1;
        }
        __syncwarp();                        // est visible within warp

        // av MMA: A = e (est, K=p tile), B = P2 tile; accumulate over d tiles
#pragma unroll
        for (int kk = 0; kk < 8; kk++) {
            const int k0 = kk * 8;
            uint32_t a[4] = { __float_as_uint(estw[grp * 68 + k0 + qid]),
                              __float_as_uint(estw[(grp + 8) * 68 + k0 + qid]),
                              __float_as_uint(estw[grp * 68 + k0 + qid + 4]),
                              __float_as_uint(estw[(grp + 8) * 68 + k0 + qid + 4]) };
#pragma unroll
            for (int t = 0; t < 8; t++) {
                uint32_t bf[2];
                load_bfr(P2s, t * 8 + grp, kk, qid, bf);
                mma_tf32(accv[t], a, bf);
            }
        }
    }

    // finalize: quad-reduce sums, write sinv + l3h
    s0 += __shfl_xor_sync(0xffffffffu, s0, 1);
    s0 += __shfl_xor_sync(0xffffffffu, s0, 2);
    s1 += __shfl_xor_sync(0xffffffffu, s1, 1);
    s1 += __shfl_xor_sync(0xffffffffu, s1, 2);
    const float inv0 = 1.0f / s0, inv1 = 1.0f / s1;
    if (qid == 0) {
        g_sinv[bh * cNL + l0 + lr0] = inv0;
        g_sinv[bh * cNL + l0 + lr1] = inv1;
    }
    const size_t orow0 = ((size_t)(b * cNL) + l0 + lr0) * 512 + h * 64;
    const size_t orow1 = ((size_t)(b * cNL) + l0 + lr1) * 512 + h * 64;
#pragma unroll
    for (int t = 0; t < 8; t++) {
        const int cc = t * 8 + 2 * qid;
        *(float2*)&g_l3h[orow0 + cc] =
            make_float2(tf32f(accv[t][0] * inv0), tf32f(accv[t][1] * inv0));
        *(float2*)&g_l3h[orow1 + cc] =
            make_float2(tf32f(accv[t][2] * inv1), tf32f(accv[t][3] * inv1));
    }
}

// =====================================================================
// atv: p3h[b,p,h*64+d] = sum_l e[l,p]*cf[l,pt] * (L2t[d,l] * sinv[l]).
// cf[l,pt] = exp(m_then[pt][l] - m_final[l]) corrects historical e scale.
// =====================================================================
__global__ __launch_bounds__(256) void atv_mma() {
    __shared__ float Ae[128 * 36];   // e^T [p][l]
    __shared__ float Bl[64 * 36];    // scaled L2t [d][l]
    __shared__ float cfa[2][256];    // corrections for this block's 2 p-tiles
#define ATS(p_, c_) Ae[(p_) * 68 + (c_)]   // epilogue stage overlays Ae
    const int bh = blockIdx.y, b = bh >> 3, h = bh & 7;
    const int p0 = blockIdx.x * 128;
    const int tid = threadIdx.x, wid = tid >> 5, lane = tid & 31, grp = lane >> 2, qid = lane & 3;
    const int m0 = wid * 16;
    const float* eb = g_att + (size_t)bh * cNL * cNP;
    const float* L2b = g_L2t + (size_t)bh * 64 * cNL;
    const float* sv = g_sinv + (size_t)bh * cNL;
    const int pt0 = p0 >> 6;

    for (int i = tid; i < 512; i += 256) {
        int v = i >> 8, j = i & 255;
        float mf = g_mthen[((size_t)bh * 32 + 31) * cNL + j];
        float mt = g_mthen[((size_t)bh * 32 + pt0 + v) * cNL + j];
        cfa[v][j] = __expf(mt - mf);
    }

    float acc[8][4] = {};
    for (int lt = 0; lt < 8; lt++) {
        const int lb = lt * 32;
        __syncthreads();   // also guards cfa readiness on first iter
        for (int i = tid; i < 4096; i += 256) {
            int r = i >> 7, c = i & 127;    // r = l local, c = p local
            Ae[c * 36 + r] = tf32f(eb[(size_t)(lb + r) * cNP + p0 + c] * cfa[c >> 6][lb + r]);
        }
        for (int i = tid; i < 2048; i += 256) {
            int d = i >> 5, k = i & 31;
            Bl[d * 36 + k] = tf32f(L2b[(size_t)d * cNL + lb + k] * sv[lb + k]);
        }
        __syncthreads();
#pragma unroll
        for (int kk = 0; kk < 4; kk++) {
            const int k0 = kk * 8;
            uint32_t a[4] = { __float_as_uint(Ae[(m0 + grp) * 36 + k0 + qid]),
                              __float_as_uint(Ae[(m0 + grp + 8) * 36 + k0 + qid]),
                              __float_as_uint(Ae[(m0 + grp) * 36 + k0 + qid + 4]),
                              __float_as_uint(Ae[(m0 + grp + 8) * 36 + k0 + qid + 4]) };
#pragma unroll
            for (int t = 0; t < 8; t++) {
                uint32_t bf[2] = { __float_as_uint(Bl[(t * 8 + grp) * 36 + k0 + qid]),
                                   __float_as_uint(Bl[(t * 8 + grp) * 36 + k0 + qid + 4]) };
                mma_tf32(acc[t], a, bf);
            }
        }
    }

#pragma unroll
    for (int half = 0; half < 2; half++) {
        __syncthreads();
        if ((wid >> 2) == half) {
            const int pl0 = (m0 & 63) + grp, pl1 = pl0 + 8;
#pragma unroll
            for (int t = 0; t < 8; t++) {
                const int c = t * 8 + 2 * qid;
                ATS(pl0, c)     = tf32f(acc[t][0]);
                ATS(pl0, c + 1) = tf32f(acc[t][1]);
                ATS(pl1, c)     = tf32f(acc[t][2]);
                ATS(pl1, c + 1) = tf32f(acc[t][3]);
            }
        }
        __syncthreads();
        const int pg = p0 + half * 64;
        for (int i = tid; i < 1024; i += 256) {
            int pl = i >> 4, c4 = (i & 15) * 4;
            *(float4*)&g_p3h[((size_t)(b * cNP) + pg + pl) * 512 + h * 64 + c4] =
                *(float4*)&ATS(pl, c4);
        }
    }
#undef ATS
}

// =====================================================================
// fc_fused (merged lig+prot): Y1 = X @ W1 + b1; out = relu([Y1, orig] @ W2 + b2).
// blocks 0..63 -> ligand; 64..575 -> prot. cp.async fills for X/W tiles.
// =====================================================================
__global__ __launch_bounds__(256) void fc_fused(const float* __restrict__ lig,
                                                const float* __restrict__ prot,
                                                const float* __restrict__ b1l,
                                                const float* __restrict__ b2l,
                                                const float* __restrict__ b1p,
                                                const float* __restrict__ b2p,
                                                float* __restrict__ out) {
    __shared__ float As[64 * 68];
    __shared__ float Bs[64 * 68];
    const int which = (blockIdx.x >= 64) ? 1 : 0;
    const int bx = which ? (blockIdx.x - 64) : blockIdx.x;
    const float* X = which ? g_p3h : g_l3h;
    const float* W1 = g_f1T[which];
    const float* W2 = g_f2T[which];
    const float* orig = which ? prot : lig;
    const float* b1 = which ? b1p : b1l;
    const float* b2 = which ? b2p : b2l;
    const int N = which ? cNP : cNL;
    const int row_off = which ? cNL : 0;
    const int row0 = bx * 64;
    const int tid = threadIdx.x, wid = tid >> 5, lane = tid & 31, grp = lane >> 2, qid = lane & 3;
    const int mtw = wid & 3, nw = wid >> 2, m0 = mtw * 16, n0 = nw * 32;
    const int r0l = m0 + grp, r1l = r0l + 8;

    // ---- fc1 ----
    float acc[4][4] = {};
    for (int kt = 0; kt < 8; kt++) {
        const int kb = kt * 64;
        __syncthreads();
        for (int i = tid; i < 1024; i += 256) {
            int r = i >> 4, k4 = (i & 15) * 4;
            cpa16(&AS(r, k4), &X[(size_t)(row0 + r) * 512 + kb + k4]);
        }
        for (int i = tid; i < 1024; i += 256) {
            int n = i >> 4, k4 = (i & 15) * 4;
            cpa16(&BS(n, k4), &W1[(size_t)n * 512 + kb + k4]);
        }
        CP_COMMIT();
        CP_WAIT(0);
        __syncthreads();
#pragma unroll
        for (int kk = 0; kk < 8; kk++) {
            uint32_t a[4];
            load_afr(As, m0, grp, qid, kk, a);
#pragma unroll
            for (int t = 0; t < 4; t++) {
                uint32_t bf[2];
                load_bfr(Bs, n0 + t * 8 + grp, kk, qid, bf);
                mma_tf32(acc[t], a, bf);
            }
        }
    }
    __syncthreads();
    // stage Y1 (tf32, no relu) into CS; load W2 kt0 tile
#pragma unroll
    for (int t = 0; t < 4; t++) {
        const int c = n0 + t * 8 + 2 * qid;
        const float bv0 = b1[c], bv1 = b1[c + 1];
        CS(r0l, c)     = tf32f(acc[t][0] + bv0);
        CS(r0l, c + 1) = tf32f(acc[t][1] + bv1);
        CS(r1l, c)     = tf32f(acc[t][2] + bv0);
        CS(r1l, c + 1) = tf32f(acc[t][3] + bv1);
    }
    for (int i = tid; i < 1024; i += 256) {
        int n = i >> 4, k4 = (i & 15) * 4;
        cpa16(&BS(n, k4), &W2[(size_t)n * 128 + k4]);
    }
    CP_COMMIT();
    CP_WAIT(0);
    __syncthreads();

    // ---- fc2, kt0 (Y1) ----
    float acc2[4][4] = {};
#pragma unroll
    for (int kk = 0; kk < 8; kk++) {
        uint32_t a[4];
        load_afr(As, m0, grp, qid, kk, a);
#pragma unroll
        for (int t = 0; t < 4; t++) {
            uint32_t bf[2];
            load_bfr(Bs, n0 + t * 8 + grp, kk, qid, bf);
            mma_tf32(acc2[t], a, bf);
        }
    }
    __syncthreads();
    // ---- fc2, kt1 (orig) ----
    for (int i = tid; i < 1024; i += 256) {
        int r = i >> 4, c4 = (i & 15) * 4;
        float4 v = *(const float4*)&orig[(size_t)(row0 + r) * 64 + c4];
        v.x = tf32f(v.x); v.y = tf32f(v.y); v.z = tf32f(v.z); v.w = tf32f(v.w);
        *(float4*)&AS(r, c4) = v;
    }
    for (int i = tid; i < 1024; i += 256) {
        int n = i >> 4, k4 = (i & 15) * 4;
        cpa16(&BS(n, k4), &W2[(size_t)n * 128 + 64 + k4]);
    }
    CP_COMMIT();
    CP_WAIT(0);
    __syncthreads();
#pragma unroll
    for (int kk = 0; kk < 8; kk++) {
        uint32_t a[4];
        load_afr(As, m0, grp, qid, kk, a);
#pragma unroll
        for (int t = 0; t < 4; t++) {
            uint32_t bf[2];
            load_bfr(Bs, n0 + t * 8 + grp, kk, qid, bf);
            mma_tf32(acc2[t], a, bf);
        }
    }
    __syncthreads();
#pragma unroll
    for (int t = 0; t < 4; t++) {
        const int c = n0 + t * 8 + 2 * qid;
        const float bv0 = b2[c], bv1 = b2[c + 1];
        CS(r0l, c)     = fmaxf(acc2[t][0] + bv0, 0.f);
        CS(r0l, c + 1) = fmaxf(acc2[t][1] + bv1, 0.f);
        CS(r1l, c)     = fmaxf(acc2[t][2] + bv0, 0.f);
        CS(r1l, c + 1) = fmaxf(acc2[t][3] + bv1, 0.f);
    }
    __syncthreads();
    const int b = row0 / N, nbase = row0 % N;
    for (int i = tid; i < 1024; i += 256) {
        int r = i >> 4, c4 = (i & 15) * 4;
        *(float4*)&out[((size_t)b * cNT + row_off + nbase + r) * 64 + c4] =
            *(float4*)&CS(r, c4);
    }
}

// =====================================================================
extern "C" void kernel_launch(void* const* d_in, const int* in_sizes, int n_in,
                              void* d_out, int out_size) {
    (void)in_sizes; (void)n_in; (void)out_size;
    const float* ligand = (const float*)d_in[0];
    const float* prot   = (const float*)d_in[1];
    const float* dist   = (const float*)d_in[2];
    const float* b_l1 = (const float*)d_in[4];
    const float* b_l2 = (const float*)d_in[6];
    const float* b_p1 = (const float*)d_in[8];
    const float* b_p2 = (const float*)d_in[10];
    const float* fc11_b = (const float*)d_in[12];
    const float* fc12_b = (const float*)d_in[14];
    const float* fc21_b = (const float*)d_in[16];
    const float* fc22_b = (const float*)d_in[18];
    float* out = (float*)d_out;

    prep_weights<<<832, 256>>>((const float*)d_in[3], (const float*)d_in[5],
                               (const float*)d_in[7], (const float*)d_in[9],
                               (const float*)d_in[11], (const float*)d_in[15],
                               (const float*)d_in[13], (const float*)d_in[17]);
    proj2<<<576, 256>>>(ligand, prot, b_l1, b_l2, b_p1, b_p2);
    energy_av<<<dim3(cNL / 64, cB * cH), 128>>>(dist);
    atv_mma<<<dim3(cNP / 128, cB * cH), 256>>>();
    fc_fused<<<576, 256>>>(ligand, prot, fc11_b, fc12_b, fc21_b, fc22_b, out);
}